// round 3
// baseline (speedup 1.0000x reference)
#include <cuda_runtime.h>

// ---------------- problem constants ----------------
#define SS   32      // source length
#define TT   32      // target length
#define BB   512     // batch
#define HH   1024    // hidden
#define EE   256     // embed
#define AA   1024    // attention dim
#define VSRC 64
#define VTGT 70
#define G3H  3072    // 3*H
#define STARTTOK 1

// ---------------- scratch (__device__ globals; no allocation) ----------------
__device__ float g_P_enc[VSRC * G3H];        // emb_src @ W_ih_enc^T
__device__ float g_P_dec[VTGT * G3H];        // emb_tgt @ W_ih_dec[:,H:]^T
__device__ float g_h[BB * HH];               // recurrent hidden state
__device__ float g_enc_ops[SS * BB * HH];    // encoder outputs       (67MB)
__device__ float g_enc_proj[SS * BB * AA];   // enc_ops @ W_attn[H:] + b_attn (67MB)
__device__ float g_hproj[BB * AA];           // h @ W_attn[:H]
__device__ float g_gh[BB * G3H];             // h @ W_hh^T
__device__ float g_gi[BB * G3H];             // ctx @ W_ih_dec[:, :H]^T
__device__ float g_ctx[BB * HH];
__device__ float g_scores[SS * BB];
__device__ int   g_x[BB];                    // decoder input token

// ---------------- SGEMM: C[M,N] = A[M,K] @ op(B) (+bias) ----------------
// TRANSB=1: B is (N,K) row-major, access B[n*ldb + k]   (y = x @ W^T, W=(out,in))
// TRANSB=0: B is (K,N) row-major, access B[k*ldb + n]
// Requires K % 16 == 0 (true here: K in {256, 1024}).
template<bool TRANSB, bool HASBIAS>
__global__ void sgemm_kernel(const float* __restrict__ A, int lda,
                             const float* __restrict__ B, int ldb,
                             const float* __restrict__ bias,
                             float* __restrict__ C, int ldc,
                             int M, int N, int K)
{
    const int BM = 128, BN = 64, BK = 16;
    __shared__ float As[BK][BM];
    __shared__ float Bs[BK][BN];
    int tx = threadIdx.x & 15;
    int ty = threadIdx.x >> 4;          // 256 threads: 16x16
    int m0 = blockIdx.y * BM;
    int n0 = blockIdx.x * BN;

    float acc[8][4];
#pragma unroll
    for (int i = 0; i < 8; i++)
#pragma unroll
        for (int j = 0; j < 4; j++) acc[i][j] = 0.f;

    for (int k0 = 0; k0 < K; k0 += BK) {
        // A tile: 128x16 = 2048 elems, 8 per thread
#pragma unroll
        for (int i = 0; i < 8; i++) {
            int t = threadIdx.x + i * 256;
            int r = t >> 4, c = t & 15;
            int gm = m0 + r;
            As[c][r] = (gm < M) ? A[(size_t)gm * lda + (k0 + c)] : 0.f;
        }
        // B tile: 16x64 = 1024 elems, 4 per thread
#pragma unroll
        for (int i = 0; i < 4; i++) {
            int t = threadIdx.x + i * 256;
            if (TRANSB) {
                int r = t >> 4, c = t & 15;         // r = n-local, c = k-local
                int gn = n0 + r;
                Bs[c][r] = (gn < N) ? B[(size_t)gn * ldb + (k0 + c)] : 0.f;
            } else {
                int r = t >> 6, c = t & 63;         // r = k-local, c = n-local
                int gn = n0 + c;
                Bs[r][c] = (gn < N) ? B[(size_t)(k0 + r) * ldb + gn] : 0.f;
            }
        }
        __syncthreads();
#pragma unroll
        for (int kk = 0; kk < BK; kk++) {
            float a[8], b[4];
#pragma unroll
            for (int i = 0; i < 8; i++) a[i] = As[kk][ty + 16 * i];
#pragma unroll
            for (int j = 0; j < 4; j++) b[j] = Bs[kk][tx + 16 * j];
#pragma unroll
            for (int i = 0; i < 8; i++)
#pragma unroll
                for (int j = 0; j < 4; j++)
                    acc[i][j] = fmaf(a[i], b[j], acc[i][j]);
        }
        __syncthreads();
    }
#pragma unroll
    for (int i = 0; i < 8; i++) {
        int gm = m0 + ty + 16 * i;
        if (gm >= M) continue;
#pragma unroll
        for (int j = 0; j < 4; j++) {
            int gn = n0 + tx + 16 * j;
            if (gn < N) {
                float v = acc[i][j];
                if (HASBIAS) v += bias[gn];
                C[(size_t)gm * ldc + gn] = v;
            }
        }
    }
}

// ---------------- init: h=0, outputs[0]=one-hot(START), x=target[0] ----------------
__global__ void init_kernel(const int* __restrict__ target, float* __restrict__ out)
{
    int i = blockIdx.x * blockDim.x + threadIdx.x;
    if (i < BB * HH) g_h[i] = 0.f;
    if (i < BB * VTGT) out[i] = ((i % VTGT) == STARTTOK) ? 1.f : 0.f;
    if (i < BB) g_x[i] = target[i];
}

// ---------------- encoder GRU cell ----------------
__global__ void gru_enc_cell(const int* __restrict__ source, int s,
                             const float* __restrict__ b_ih,
                             const float* __restrict__ b_hh)
{
    int idx = blockIdx.x * blockDim.x + threadIdx.x;
    if (idx >= BB * HH) return;
    int b = idx / HH, j = idx - b * HH;
    int tok = source[s * BB + b];
    const float* P  = &g_P_enc[(size_t)tok * G3H];
    const float* gh = &g_gh[(size_t)b * G3H];
    float gir = P[j]          + b_ih[j];
    float giz = P[HH + j]     + b_ih[HH + j];
    float gin = P[2 * HH + j] + b_ih[2 * HH + j];
    float ghr = gh[j]          + b_hh[j];
    float ghz = gh[HH + j]     + b_hh[HH + j];
    float ghn = gh[2 * HH + j] + b_hh[2 * HH + j];
    float r = 1.f / (1.f + expf(-(gir + ghr)));
    float z = 1.f / (1.f + expf(-(giz + ghz)));
    float n = tanhf(gin + r * ghn);
    float hv = (1.f - z) * n + z * g_h[idx];
    g_h[idx] = hv;
    g_enc_ops[(size_t)s * BB * HH + idx] = hv;
}

// ---------------- decoder GRU cell ----------------
__global__ void gru_dec_cell(const float* __restrict__ b_ih,
                             const float* __restrict__ b_hh)
{
    int idx = blockIdx.x * blockDim.x + threadIdx.x;
    if (idx >= BB * HH) return;
    int b = idx / HH, j = idx - b * HH;
    int tok = g_x[b];
    const float* P  = &g_P_dec[(size_t)tok * G3H];
    const float* gi = &g_gi[(size_t)b * G3H];
    const float* gh = &g_gh[(size_t)b * G3H];
    float gir = gi[j]          + P[j]          + b_ih[j];
    float giz = gi[HH + j]     + P[HH + j]     + b_ih[HH + j];
    float gin = gi[2 * HH + j] + P[2 * HH + j] + b_ih[2 * HH + j];
    float ghr = gh[j]          + b_hh[j];
    float ghz = gh[HH + j]     + b_hh[HH + j];
    float ghn = gh[2 * HH + j] + b_hh[2 * HH + j];
    float r = 1.f / (1.f + expf(-(gir + ghr)));
    float z = 1.f / (1.f + expf(-(giz + ghz)));
    float n = tanhf(gin + r * ghn);
    g_h[idx] = (1.f - z) * n + z * g_h[idx];
}

// ---------------- attention scores: scores[s,b] = sum_a tanh(enc_proj + hproj) * v ----------------
__global__ void attn_scores_kernel(const float* __restrict__ v_attn)
{
    int row = blockIdx.x;                 // s*BB + b
    int b = row % BB;
    const float* ep = &g_enc_proj[(size_t)row * AA];
    const float* hp = &g_hproj[(size_t)b * AA];
    float sum = 0.f;
    for (int a = threadIdx.x; a < AA; a += 256)
        sum += tanhf(ep[a] + hp[a]) * v_attn[a];
    __shared__ float red[256];
    red[threadIdx.x] = sum;
    __syncthreads();
#pragma unroll
    for (int off = 128; off > 0; off >>= 1) {
        if (threadIdx.x < off) red[threadIdx.x] += red[threadIdx.x + off];
        __syncthreads();
    }
    if (threadIdx.x == 0) g_scores[row] = red[0];
}

// ---------------- softmax over s + context + attn output ----------------
__global__ void softmax_ctx_kernel(float* __restrict__ attn_plane /* (B,S) */)
{
    int b = blockIdx.x;
    __shared__ float alpha[SS];
    if (threadIdx.x < SS) alpha[threadIdx.x] = g_scores[threadIdx.x * BB + b];
    __syncthreads();
    if (threadIdx.x == 0) {
        float mx = -1e30f;
        for (int s = 0; s < SS; s++) mx = fmaxf(mx, alpha[s]);
        float sm = 0.f;
        for (int s = 0; s < SS; s++) { alpha[s] = expf(alpha[s] - mx); sm += alpha[s]; }
        float inv = 1.f / sm;
        for (int s = 0; s < SS; s++) alpha[s] *= inv;
    }
    __syncthreads();
    if (threadIdx.x < SS) attn_plane[b * SS + threadIdx.x] = alpha[threadIdx.x];
    for (int h = threadIdx.x; h < HH; h += 256) {
        float acc = 0.f;
#pragma unroll
        for (int s = 0; s < SS; s++)
            acc += alpha[s] * g_enc_ops[((size_t)s * BB + b) * HH + h];
        g_ctx[(size_t)b * HH + h] = acc;
    }
}

// ---------------- logits + next-token (teacher forcing or argmax) ----------------
__global__ void logits_kernel(const float* __restrict__ W_out,  // (H, VT) row-major
                              const float* __restrict__ b_out,
                              const int* __restrict__ target,
                              const int* __restrict__ tf_ptr,
                              int t, float* __restrict__ out)
{
    int b = blockIdx.x;
    __shared__ float hs[HH];
    for (int k = threadIdx.x; k < HH; k += 128) hs[k] = g_h[(size_t)b * HH + k];
    __syncthreads();
    int v = threadIdx.x;
    float lg = -1e30f;
    if (v < VTGT) {
        float acc = b_out[v];
        for (int k = 0; k < HH; k++) acc = fmaf(hs[k], W_out[k * VTGT + v], acc);
        out[(size_t)t * BB * VTGT + (size_t)b * VTGT + v] = acc;
        lg = acc;
    }
    __shared__ float sv[128];
    __shared__ int   si[128];
    sv[threadIdx.x] = lg;
    si[threadIdx.x] = v;
    __syncthreads();
#pragma unroll
    for (int off = 64; off > 0; off >>= 1) {
        if (threadIdx.x < off) {
            float vo = sv[threadIdx.x + off];
            int   io = si[threadIdx.x + off];
            if (vo > sv[threadIdx.x] || (vo == sv[threadIdx.x] && io < si[threadIdx.x])) {
                sv[threadIdx.x] = vo;
                si[threadIdx.x] = io;
            }
        }
        __syncthreads();
    }
    if (threadIdx.x == 0)
        g_x[b] = (*tf_ptr != 0) ? target[t * BB + b] : si[0];
}

// ---------------- host-side orchestration ----------------
static inline void gemm(const float* A, int lda, const float* B, int ldb,
                        const float* bias, float* C, int ldc,
                        int M, int N, int K, bool transB)
{
    dim3 grid((N + 63) / 64, (M + 127) / 128);
    if (transB)
        sgemm_kernel<true, false><<<grid, 256>>>(A, lda, B, ldb, nullptr, C, ldc, M, N, K);
    else if (bias)
        sgemm_kernel<false, true><<<grid, 256>>>(A, lda, B, ldb, bias, C, ldc, M, N, K);
    else
        sgemm_kernel<false, false><<<grid, 256>>>(A, lda, B, ldb, nullptr, C, ldc, M, N, K);
}

extern "C" void kernel_launch(void* const* d_in, const int* in_sizes, int n_in,
                              void* d_out, int out_size)
{
    const int*   source   = (const int*)  d_in[0];
    const int*   target   = (const int*)  d_in[1];
    const int*   tf       = (const int*)  d_in[2];
    const float* emb_src  = (const float*)d_in[3];
    const float* W_ih_enc = (const float*)d_in[4];
    const float* W_hh_enc = (const float*)d_in[5];
    const float* b_ih_enc = (const float*)d_in[6];
    const float* b_hh_enc = (const float*)d_in[7];
    const float* emb_tgt  = (const float*)d_in[8];
    const float* W_attn   = (const float*)d_in[9];
    const float* b_attn   = (const float*)d_in[10];
    const float* v_attn   = (const float*)d_in[11];
    const float* W_ih_dec = (const float*)d_in[12];
    const float* W_hh_dec = (const float*)d_in[13];
    const float* b_ih_dec = (const float*)d_in[14];
    const float* b_hh_dec = (const float*)d_in[15];
    const float* W_out    = (const float*)d_in[16];
    const float* b_out    = (const float*)d_in[17];

    float* out      = (float*)d_out;
    float* attn_out = out + (size_t)TT * BB * VTGT;

    float *pP_enc, *pP_dec, *ph, *penc, *pproj, *phproj, *pgh, *pgi, *pctx;
    cudaGetSymbolAddress((void**)&pP_enc, g_P_enc);
    cudaGetSymbolAddress((void**)&pP_dec, g_P_dec);
    cudaGetSymbolAddress((void**)&ph,     g_h);
    cudaGetSymbolAddress((void**)&penc,   g_enc_ops);
    cudaGetSymbolAddress((void**)&pproj,  g_enc_proj);
    cudaGetSymbolAddress((void**)&phproj, g_hproj);
    cudaGetSymbolAddress((void**)&pgh,    g_gh);
    cudaGetSymbolAddress((void**)&pgi,    g_gi);
    cudaGetSymbolAddress((void**)&pctx,   g_ctx);

    // init: h=0, outputs row 0, x = target[0]
    init_kernel<<<(BB * HH + 255) / 256, 256>>>(target, out);

    // token-projection tables (fold embedding gather through the input GEMMs)
    gemm(emb_src, EE, W_ih_enc, EE, nullptr, pP_enc, G3H, VSRC, G3H, EE, true);
    gemm(emb_tgt, EE, W_ih_dec + HH, HH + EE, nullptr, pP_dec, G3H, VTGT, G3H, EE, true);

    // ---------------- encoder ----------------
    for (int s = 0; s < SS; s++) {
        gemm(ph, HH, W_hh_enc, HH, nullptr, pgh, G3H, BB, G3H, HH, true);
        gru_enc_cell<<<(BB * HH + 255) / 256, 256>>>(source, s, b_ih_enc, b_hh_enc);
    }

    // step-invariant half of the attention energy (+ bias folded in)
    gemm(penc, HH, W_attn + (size_t)HH * AA, AA, b_attn, pproj, AA, SS * BB, AA, HH, false);

    // ---------------- decoder ----------------
    for (int t = 1; t < TT; t++) {
        gemm(ph, HH, W_attn, AA, nullptr, phproj, AA, BB, AA, HH, false);
        attn_scores_kernel<<<SS * BB, 256>>>(v_attn);
        softmax_ctx_kernel<<<BB, 256>>>(attn_out + (size_t)(t - 1) * BB * SS);
        gemm(ph,   HH, W_hh_dec, HH,      nullptr, pgh, G3H, BB, G3H, HH, true);
        gemm(pctx, HH, W_ih_dec, HH + EE, nullptr, pgi, G3H, BB, G3H, HH, true);
        gru_dec_cell<<<(BB * HH + 255) / 256, 256>>>(b_ih_dec, b_hh_dec);
        logits_kernel<<<BB, 128>>>(W_out, b_out, target, tf, t, out);
    }
}

// round 4
// speedup vs baseline: 3.1128x; 3.1128x over previous
#include <cuda_runtime.h>

// ---------------- problem constants ----------------
#define SS   32      // source length
#define TT   32      // target length
#define BB   512     // batch
#define HH   1024    // hidden
#define EE   256     // embed
#define AA   1024    // attention dim
#define VSRC 64
#define VTGT 70
#define G3H  3072    // 3*H
#define NCAT 4096    // 3H (gh) + A (hproj) fused decoder GEMM width
#define STARTTOK 1

// ---------------- scratch (__device__ globals; no allocation) ----------------
__device__ float g_P_enc[VSRC * G3H];        // emb_src @ W_ih_enc^T
__device__ float g_P_dec[VTGT * G3H];        // emb_tgt @ W_ih_dec[:,H:]^T
__device__ float g_Wcat[NCAT * HH];          // [W_hh_dec ; W_attn[:H]^T] (n,k) layout
__device__ float g_h[BB * HH];               // recurrent hidden state
__device__ float g_enc_ops[SS * BB * HH];    // encoder outputs         (67MB)
__device__ float g_enc_proj[SS * BB * AA];   // enc_ops@W_attn[H:]+b    (67MB)
__device__ float g_gh[BB * G3H];             // encoder: h @ W_hh_enc^T
__device__ float g_ghp[BB * NCAT];           // decoder: h @ Wcat^T  (gh | hproj)
__device__ float g_gi[BB * G3H];             // ctx @ W_ih_dec[:, :H]^T
__device__ float g_ctx[BB * HH];
__device__ int   g_x[BB];                    // decoder input token

__device__ __forceinline__ float tanh_fast(float x) {
    float y;
    asm("tanh.approx.f32 %0, %1;" : "=f"(y) : "f"(x));
    return y;
}
__device__ __forceinline__ float sigmoid_f(float x) {
    return 1.f / (1.f + __expf(-x));
}

// ---------------- SGEMM: C[M,N] = A[M,K] @ op(B) (+bias) ----------------
// 128x64x16 tile, 128 threads, 8x8 per-thread register tile, float4 everywhere,
// double-buffered smem. Requires: K % 16 == 0, N % 64 == 0, A/B/C rows 16B-aligned.
// TRANSB=1: B is (N,K) row-major.  TRANSB=0: B is (K,N) row-major.
#define BM 128
#define BN 64
#define BK 16
#define ASTR (BM + 4)   // 132: pad kills transpose-scatter bank conflicts
#define BSTR (BN + 4)   // 68

template<bool TRANSB, bool HASBIAS>
__global__ __launch_bounds__(128)
void sgemm_kernel(const float* __restrict__ A, int lda,
                  const float* __restrict__ B, int ldb,
                  const float* __restrict__ bias,
                  float* __restrict__ C, int ldc,
                  int M, int N, int K)
{
    __shared__ float As[2][BK * ASTR];
    __shared__ float Bs[2][BK * BSTR];

    const int tid = threadIdx.x;
    const int m0 = blockIdx.y * BM;
    const int n0 = blockIdx.x * BN;
    const int tm = (tid >> 3) * 8;   // 0..120
    const int tn = (tid & 7) * 8;    // 0..56

    float acc[8][8];
#pragma unroll
    for (int i = 0; i < 8; i++)
#pragma unroll
        for (int j = 0; j < 8; j++) acc[i][j] = 0.f;

    float4 ra[4], rb[2];

    // ---- load tile 0 into regs ----
#pragma unroll
    for (int i = 0; i < 4; i++) {
        int f = tid + i * 128;           // f4 index in 128x16 A tile
        int r = f >> 2, kc = (f & 3) * 4;
        int gm = m0 + r;
        ra[i] = (gm < M) ? *(const float4*)&A[(size_t)gm * lda + kc]
                         : make_float4(0.f, 0.f, 0.f, 0.f);
    }
#pragma unroll
    for (int i = 0; i < 2; i++) {
        int f = tid + i * 128;
        if (TRANSB) {
            int r = f >> 2, kc = (f & 3) * 4;
            rb[i] = *(const float4*)&B[(size_t)(n0 + r) * ldb + kc];
        } else {
            int k = f >> 4, nn = (f & 15) * 4;
            rb[i] = *(const float4*)&B[(size_t)k * ldb + n0 + nn];
        }
    }
    // ---- store tile 0 ----
#pragma unroll
    for (int i = 0; i < 4; i++) {
        int f = tid + i * 128;
        int r = f >> 2, kc = (f & 3) * 4;
        As[0][(kc + 0) * ASTR + r] = ra[i].x;
        As[0][(kc + 1) * ASTR + r] = ra[i].y;
        As[0][(kc + 2) * ASTR + r] = ra[i].z;
        As[0][(kc + 3) * ASTR + r] = ra[i].w;
    }
#pragma unroll
    for (int i = 0; i < 2; i++) {
        int f = tid + i * 128;
        if (TRANSB) {
            int r = f >> 2, kc = (f & 3) * 4;
            Bs[0][(kc + 0) * BSTR + r] = rb[i].x;
            Bs[0][(kc + 1) * BSTR + r] = rb[i].y;
            Bs[0][(kc + 2) * BSTR + r] = rb[i].z;
            Bs[0][(kc + 3) * BSTR + r] = rb[i].w;
        } else {
            int k = f >> 4, nn = (f & 15) * 4;
            *(float4*)&Bs[0][k * BSTR + nn] = rb[i];
        }
    }
    __syncthreads();

    const int nk = K / BK;
    for (int kt = 0; kt < nk; kt++) {
        const int buf = kt & 1;
        const int knext = (kt + 1) * BK;
        if (kt + 1 < nk) {
            // prefetch next tile to regs (overlaps with compute)
#pragma unroll
            for (int i = 0; i < 4; i++) {
                int f = tid + i * 128;
                int r = f >> 2, kc = (f & 3) * 4;
                int gm = m0 + r;
                ra[i] = (gm < M) ? *(const float4*)&A[(size_t)gm * lda + knext + kc]
                                 : make_float4(0.f, 0.f, 0.f, 0.f);
            }
#pragma unroll
            for (int i = 0; i < 2; i++) {
                int f = tid + i * 128;
                if (TRANSB) {
                    int r = f >> 2, kc = (f & 3) * 4;
                    rb[i] = *(const float4*)&B[(size_t)(n0 + r) * ldb + knext + kc];
                } else {
                    int k = f >> 4, nn = (f & 15) * 4;
                    rb[i] = *(const float4*)&B[(size_t)(knext + k) * ldb + n0 + nn];
                }
            }
        }
#pragma unroll
        for (int kk = 0; kk < BK; kk++) {
            float4 a0 = *(const float4*)&As[buf][kk * ASTR + tm];
            float4 a1 = *(const float4*)&As[buf][kk * ASTR + tm + 4];
            float4 b0 = *(const float4*)&Bs[buf][kk * BSTR + tn];
            float4 b1 = *(const float4*)&Bs[buf][kk * BSTR + tn + 4];
            float av[8] = {a0.x, a0.y, a0.z, a0.w, a1.x, a1.y, a1.z, a1.w};
            float bv[8] = {b0.x, b0.y, b0.z, b0.w, b1.x, b1.y, b1.z, b1.w};
#pragma unroll
            for (int i = 0; i < 8; i++)
#pragma unroll
                for (int j = 0; j < 8; j++)
                    acc[i][j] = fmaf(av[i], bv[j], acc[i][j]);
        }
        if (kt + 1 < nk) {
            const int nbuf = buf ^ 1;
#pragma unroll
            for (int i = 0; i < 4; i++) {
                int f = tid + i * 128;
                int r = f >> 2, kc = (f & 3) * 4;
                As[nbuf][(kc + 0) * ASTR + r] = ra[i].x;
                As[nbuf][(kc + 1) * ASTR + r] = ra[i].y;
                As[nbuf][(kc + 2) * ASTR + r] = ra[i].z;
                As[nbuf][(kc + 3) * ASTR + r] = ra[i].w;
            }
#pragma unroll
            for (int i = 0; i < 2; i++) {
                int f = tid + i * 128;
                if (TRANSB) {
                    int r = f >> 2, kc = (f & 3) * 4;
                    Bs[nbuf][(kc + 0) * BSTR + r] = rb[i].x;
                    Bs[nbuf][(kc + 1) * BSTR + r] = rb[i].y;
                    Bs[nbuf][(kc + 2) * BSTR + r] = rb[i].z;
                    Bs[nbuf][(kc + 3) * BSTR + r] = rb[i].w;
                } else {
                    int k = f >> 4, nn = (f & 15) * 4;
                    *(float4*)&Bs[nbuf][k * BSTR + nn] = rb[i];
                }
            }
            __syncthreads();
        }
    }

    // ---- epilogue ----
    float bv[8];
    if (HASBIAS) {
#pragma unroll
        for (int j = 0; j < 8; j++) bv[j] = bias[n0 + tn + j];
    }
#pragma unroll
    for (int i = 0; i < 8; i++) {
        int gm = m0 + tm + i;
        if (gm >= M) continue;
        float4 c0, c1;
        c0.x = acc[i][0]; c0.y = acc[i][1]; c0.z = acc[i][2]; c0.w = acc[i][3];
        c1.x = acc[i][4]; c1.y = acc[i][5]; c1.z = acc[i][6]; c1.w = acc[i][7];
        if (HASBIAS) {
            c0.x += bv[0]; c0.y += bv[1]; c0.z += bv[2]; c0.w += bv[3];
            c1.x += bv[4]; c1.y += bv[5]; c1.z += bv[6]; c1.w += bv[7];
        }
        float* crow = &C[(size_t)gm * ldc + n0 + tn];
        *(float4*)&crow[0] = c0;
        *(float4*)&crow[4] = c1;
    }
}

// ---------------- init: h=0, outputs[0]=one-hot(START), x=target[0] ----------------
__global__ void init_kernel(const int* __restrict__ target, float* __restrict__ out)
{
    int i = blockIdx.x * blockDim.x + threadIdx.x;
    if (i < BB * HH) g_h[i] = 0.f;
    if (i < BB * VTGT) out[i] = ((i % VTGT) == STARTTOK) ? 1.f : 0.f;
    if (i < BB) g_x[i] = target[i];
}

// ---------------- build fused decoder weight: [W_hh_dec ; W_attn[:H]^T] ----------------
__global__ void build_wcat(const float* __restrict__ W_hh_dec,
                           const float* __restrict__ W_attn)
{
    int idx = blockIdx.x * blockDim.x + threadIdx.x;
    if (idx >= NCAT * HH) return;
    int n = idx / HH, k = idx - n * HH;
    g_Wcat[idx] = (n < G3H) ? W_hh_dec[idx]
                            : W_attn[(size_t)k * AA + (n - G3H)];
}

// ---------------- encoder GRU cell ----------------
__global__ void gru_enc_cell(const int* __restrict__ source, int s,
                             const float* __restrict__ b_ih,
                             const float* __restrict__ b_hh)
{
    int idx = blockIdx.x * blockDim.x + threadIdx.x;
    if (idx >= BB * HH) return;
    int b = idx / HH, j = idx - b * HH;
    int tok = source[s * BB + b];
    const float* P  = &g_P_enc[(size_t)tok * G3H];
    const float* gh = &g_gh[(size_t)b * G3H];
    float gir = P[j]          + b_ih[j];
    float giz = P[HH + j]     + b_ih[HH + j];
    float gin = P[2 * HH + j] + b_ih[2 * HH + j];
    float ghr = gh[j]          + b_hh[j];
    float ghz = gh[HH + j]     + b_hh[HH + j];
    float ghn = gh[2 * HH + j] + b_hh[2 * HH + j];
    float r = sigmoid_f(gir + ghr);
    float z = sigmoid_f(giz + ghz);
    float n = tanhf(gin + r * ghn);
    float hv = (1.f - z) * n + z * g_h[idx];
    g_h[idx] = hv;
    g_enc_ops[(size_t)s * BB * HH + idx] = hv;
}

// ---------------- decoder GRU cell (gh from fused g_ghp, stride NCAT) ----------------
__global__ void gru_dec_cell(const float* __restrict__ b_ih,
                             const float* __restrict__ b_hh)
{
    int idx = blockIdx.x * blockDim.x + threadIdx.x;
    if (idx >= BB * HH) return;
    int b = idx / HH, j = idx - b * HH;
    int tok = g_x[b];
    const float* P  = &g_P_dec[(size_t)tok * G3H];
    const float* gi = &g_gi[(size_t)b * G3H];
    const float* gh = &g_ghp[(size_t)b * NCAT];
    float gir = gi[j]          + P[j]          + b_ih[j];
    float giz = gi[HH + j]     + P[HH + j]     + b_ih[HH + j];
    float gin = gi[2 * HH + j] + P[2 * HH + j] + b_ih[2 * HH + j];
    float ghr = gh[j]          + b_hh[j];
    float ghz = gh[HH + j]     + b_hh[HH + j];
    float ghn = gh[2 * HH + j] + b_hh[2 * HH + j];
    float r = sigmoid_f(gir + ghr);
    float z = sigmoid_f(giz + ghz);
    float n = tanhf(gin + r * ghn);
    g_h[idx] = (1.f - z) * n + z * g_h[idx];
}

// ---------------- fused attention: scores -> softmax -> context ----------------
// One block per batch element b; 1024 threads (32 warps). Warp w owns source pos s=w.
__global__ __launch_bounds__(1024)
void attn_fused_kernel(const float* __restrict__ v_attn,
                       float* __restrict__ attn_plane /* (B,S) */)
{
    int b = blockIdx.x;
    int tid = threadIdx.x;
    int w = tid >> 5, lane = tid & 31;

    __shared__ float hp_s[AA];
    __shared__ float v_s[AA];
    __shared__ float sc[SS];
    __shared__ float alpha_s[SS];

    hp_s[tid] = g_ghp[(size_t)b * NCAT + G3H + tid];   // hproj lives after gh
    v_s[tid]  = v_attn[tid];
    __syncthreads();

    // score[s=w] = sum_a tanh(enc_proj[s,b,a] + hproj[b,a]) * v[a]
    const float* ep = &g_enc_proj[((size_t)w * BB + b) * AA];
    float sum = 0.f;
#pragma unroll
    for (int i = 0; i < AA / 32; i++) {
        int a = i * 32 + lane;
        sum += tanh_fast(ep[a] + hp_s[a]) * v_s[a];
    }
#pragma unroll
    for (int off = 16; off > 0; off >>= 1)
        sum += __shfl_xor_sync(0xffffffffu, sum, off);
    if (lane == 0) sc[w] = sum;
    __syncthreads();

    // softmax over s (warp 0, lane = s)
    if (w == 0) {
        float v = sc[lane];
        float mx = v;
#pragma unroll
        for (int off = 16; off > 0; off >>= 1)
            mx = fmaxf(mx, __shfl_xor_sync(0xffffffffu, mx, off));
        float e = __expf(v - mx);
        float ssum = e;
#pragma unroll
        for (int off = 16; off > 0; off >>= 1)
            ssum += __shfl_xor_sync(0xffffffffu, ssum, off);
        float al = e / ssum;
        alpha_s[lane] = al;
        attn_plane[b * SS + lane] = al;
    }
    __syncthreads();

    // ctx[b,h] = sum_s alpha[s] * enc_ops[s,b,h]   (tid = h)
    float accv = 0.f;
#pragma unroll
    for (int s = 0; s < SS; s++)
        accv = fmaf(alpha_s[s], g_enc_ops[((size_t)s * BB + b) * HH + tid], accv);
    g_ctx[(size_t)b * HH + tid] = accv;
}

// ---------------- logits + next-token (teacher forcing or argmax) ----------------
__global__ void logits_kernel(const float* __restrict__ W_out,  // (H, VT) row-major
                              const float* __restrict__ b_out,
                              const int* __restrict__ target,
                              const int* __restrict__ tf_ptr,
                              int t, float* __restrict__ out)
{
    int b = blockIdx.x;
    __shared__ float hs[HH];
    for (int k = threadIdx.x; k < HH; k += 128) hs[k] = g_h[(size_t)b * HH + k];
    __syncthreads();
    int v = threadIdx.x;
    float lg = -1e30f;
    if (v < VTGT) {
        float acc = b_out[v];
#pragma unroll 8
        for (int k = 0; k < HH; k++) acc = fmaf(hs[k], W_out[k * VTGT + v], acc);
        out[(size_t)t * BB * VTGT + (size_t)b * VTGT + v] = acc;
        lg = acc;
    }
    __shared__ float sv[128];
    __shared__ int   si[128];
    sv[threadIdx.x] = lg;
    si[threadIdx.x] = v;
    __syncthreads();
#pragma unroll
    for (int off = 64; off > 0; off >>= 1) {
        if (threadIdx.x < off) {
            float vo = sv[threadIdx.x + off];
            int   io = si[threadIdx.x + off];
            if (vo > sv[threadIdx.x] || (vo == sv[threadIdx.x] && io < si[threadIdx.x])) {
                sv[threadIdx.x] = vo;
                si[threadIdx.x] = io;
            }
        }
        __syncthreads();
    }
    if (threadIdx.x == 0)
        g_x[b] = (*tf_ptr != 0) ? target[t * BB + b] : si[0];
}

// ---------------- host-side orchestration ----------------
static inline void gemm(const float* A, int lda, const float* B, int ldb,
                        const float* bias, float* C, int ldc,
                        int M, int N, int K, bool transB)
{
    dim3 grid(N / BN, (M + BM - 1) / BM);
    if (transB)
        sgemm_kernel<true, false><<<grid, 128>>>(A, lda, B, ldb, nullptr, C, ldc, M, N, K);
    else if (bias)
        sgemm_kernel<false, true><<<grid, 128>>>(A, lda, B, ldb, bias, C, ldc, M, N, K);
    else
        sgemm_kernel<false, false><<<grid, 128>>>(A, lda, B, ldb, nullptr, C, ldc, M, N, K);
}

extern "C" void kernel_launch(void* const* d_in, const int* in_sizes, int n_in,
                              void* d_out, int out_size)
{
    const int*   source   = (const int*)  d_in[0];
    const int*   target   = (const int*)  d_in[1];
    const int*   tf       = (const int*)  d_in[2];
    const float* emb_src  = (const float*)d_in[3];
    const float* W_ih_enc = (const float*)d_in[4];
    const float* W_hh_enc = (const float*)d_in[5];
    const float* b_ih_enc = (const float*)d_in[6];
    const float* b_hh_enc = (const float*)d_in[7];
    const float* emb_tgt  = (const float*)d_in[8];
    const float* W_attn   = (const float*)d_in[9];
    const float* b_attn   = (const float*)d_in[10];
    const float* v_attn   = (const float*)d_in[11];
    const float* W_ih_dec = (const float*)d_in[12];
    const float* W_hh_dec = (const float*)d_in[13];
    const float* b_ih_dec = (const float*)d_in[14];
    const float* b_hh_dec = (const float*)d_in[15];
    const float* W_out    = (const float*)d_in[16];
    const float* b_out    = (const float*)d_in[17];

    float* out      = (float*)d_out;
    float* attn_out = out + (size_t)TT * BB * VTGT;

    float *pP_enc, *pP_dec, *ph, *penc, *pproj, *pgh, *pghp, *pgi, *pctx, *pWcat;
    cudaGetSymbolAddress((void**)&pP_enc, g_P_enc);
    cudaGetSymbolAddress((void**)&pP_dec, g_P_dec);
    cudaGetSymbolAddress((void**)&ph,     g_h);
    cudaGetSymbolAddress((void**)&penc,   g_enc_ops);
    cudaGetSymbolAddress((void**)&pproj,  g_enc_proj);
    cudaGetSymbolAddress((void**)&pgh,    g_gh);
    cudaGetSymbolAddress((void**)&pghp,   g_ghp);
    cudaGetSymbolAddress((void**)&pgi,    g_gi);
    cudaGetSymbolAddress((void**)&pctx,   g_ctx);
    cudaGetSymbolAddress((void**)&pWcat,  g_Wcat);

    // init: h=0, outputs row 0, x = target[0]
    init_kernel<<<(BB * HH + 255) / 256, 256>>>(target, out);

    // token-projection tables (fold embedding gather through the input GEMMs)
    gemm(emb_src, EE, W_ih_enc, EE, nullptr, pP_enc, G3H, VSRC, G3H, EE, true);
    gemm(emb_tgt, EE, W_ih_dec + HH, HH + EE, nullptr, pP_dec, G3H, VTGT, G3H, EE, true);

    // fused decoder weight [W_hh_dec ; W_attn[:H]^T]
    build_wcat<<<(NCAT * HH + 255) / 256, 256>>>(W_hh_dec, W_attn);

    // ---------------- encoder ----------------
    for (int s = 0; s < SS; s++) {
        gemm(ph, HH, W_hh_enc, HH, nullptr, pgh, G3H, BB, G3H, HH, true);
        gru_enc_cell<<<(BB * HH + 255) / 256, 256>>>(source, s, b_ih_enc, b_hh_enc);
    }

    // step-invariant half of the attention energy (+ bias folded in)
    gemm(penc, HH, W_attn + (size_t)HH * AA, AA, b_attn, pproj, AA, SS * BB, AA, HH, false);

    // ---------------- decoder ----------------
    for (int t = 1; t < TT; t++) {
        // one fused GEMM: h -> [gh (3072) | hproj (1024)]
        gemm(ph, HH, pWcat, HH, nullptr, pghp, NCAT, BB, NCAT, HH, true);
        attn_fused_kernel<<<BB, 1024>>>(v_attn, attn_out + (size_t)(t - 1) * BB * SS);
        gemm(pctx, HH, W_ih_dec, HH + EE, nullptr, pgi, G3H, BB, G3H, HH, true);
        gru_dec_cell<<<(BB * HH + 255) / 256, 256>>>(b_ih_dec, b_hh_dec);
        logits_kernel<<<BB, 128>>>(W_out, b_out, target, tf, t, out);
    }
}

// round 5
// speedup vs baseline: 3.4529x; 1.1093x over previous
#include <cuda_runtime.h>

// ---------------- problem constants ----------------
#define SS   32      // source length
#define TT   32      // target length
#define BB   512     // batch
#define HH   1024    // hidden
#define EE   256     // embed
#define AA   1024    // attention dim
#define VSRC 64
#define VTGT 70
#define G3H  3072    // 3*H
#define NCAT 4096    // 3H (gh) + A (hproj) fused decoder GEMM width
#define STARTTOK 1

typedef unsigned long long ull;

// ---------------- scratch (__device__ globals; no allocation) ----------------
__device__ float g_P_enc[VSRC * G3H];        // emb_src @ W_ih_enc^T
__device__ float g_P_dec[VTGT * G3H];        // emb_tgt @ W_ih_dec[:,H:]^T
__device__ float g_Wcat[NCAT * HH];          // [W_hh_dec ; W_attn[:H]^T] (n,k) layout
__device__ float g_h[BB * HH];               // recurrent hidden state
__device__ float g_enc_ops[SS * BB * HH];    // encoder outputs         (67MB)
__device__ float g_enc_proj[SS * BB * AA];   // enc_ops@W_attn[H:]+b    (67MB)
__device__ float g_gh[BB * G3H];             // encoder: h @ W_hh_enc^T
__device__ float g_ghp[BB * NCAT];           // decoder: h @ Wcat^T  (gh | hproj)
__device__ float g_gi[BB * G3H];             // ctx @ W_ih_dec[:, :H]^T
__device__ float g_ctx[BB * HH];
__device__ int   g_x[BB];                    // decoder input token

__device__ __forceinline__ float tanh_fast(float x) {
    float y;
    asm("tanh.approx.f32 %0, %1;" : "=f"(y) : "f"(x));
    return y;
}
__device__ __forceinline__ float sigmoid_f(float x) {
    return 1.f / (1.f + __expf(-x));
}

// packed fp32 helpers (sm_103a FFMA2 pipe — only reachable via PTX f32x2)
__device__ __forceinline__ ull pack_dup(float a) {
    ull r;
    asm("mov.b64 %0, {%1, %1};" : "=l"(r) : "f"(a));
    return r;
}
__device__ __forceinline__ void fma_x2(ull& acc, ull a, ull b) {
    asm("fma.rn.f32x2 %0, %1, %2, %0;" : "+l"(acc) : "l"(a), "l"(b));
}

// ---------------- SGEMM: C[M,N] = A[M,K] @ op(B) (+bias) ----------------
// 128x64x16 tile, 128 threads, 8x8 per-thread register tile (packed f32x2 in N),
// float4 LDG/LDS, double-buffered smem. Requires: K % 16 == 0, N % 64 == 0,
// A/B/C rows 16B-aligned.
// TRANSB=1: B is (N,K) row-major.  TRANSB=0: B is (K,N) row-major.
#define BM 128
#define BN 64
#define BK 16
#define ASTR (BM + 4)   // 132: pad kills transpose-scatter bank conflicts
#define BSTR (BN + 4)   // 68

template<bool TRANSB, bool HASBIAS>
__global__ __launch_bounds__(128)
void sgemm_kernel(const float* __restrict__ A, int lda,
                  const float* __restrict__ B, int ldb,
                  const float* __restrict__ bias,
                  float* __restrict__ C, int ldc,
                  int M, int N, int K)
{
    __shared__ float As[2][BK * ASTR];
    __shared__ float Bs[2][BK * BSTR];

    const int tid = threadIdx.x;
    const int m0 = blockIdx.y * BM;
    const int n0 = blockIdx.x * BN;
    const int tm = (tid >> 3) * 8;   // 0..120
    const int tn = (tid & 7) * 8;    // 0..56

    // packed accumulators: acc[i][j] covers C[tm+i][tn+2j .. tn+2j+1]
    ull acc[8][4];
#pragma unroll
    for (int i = 0; i < 8; i++)
#pragma unroll
        for (int j = 0; j < 4; j++) acc[i][j] = 0ull;

    float4 ra[4], rb[2];

    // ---- load tile 0 into regs ----
#pragma unroll
    for (int i = 0; i < 4; i++) {
        int f = tid + i * 128;           // f4 index in 128x16 A tile
        int r = f >> 2, kc = (f & 3) * 4;
        int gm = m0 + r;
        ra[i] = (gm < M) ? *(const float4*)&A[(size_t)gm * lda + kc]
                         : make_float4(0.f, 0.f, 0.f, 0.f);
    }
#pragma unroll
    for (int i = 0; i < 2; i++) {
        int f = tid + i * 128;
        if (TRANSB) {
            int r = f >> 2, kc = (f & 3) * 4;
            rb[i] = *(const float4*)&B[(size_t)(n0 + r) * ldb + kc];
        } else {
            int k = f >> 4, nn = (f & 15) * 4;
            rb[i] = *(const float4*)&B[(size_t)k * ldb + n0 + nn];
        }
    }
    // ---- store tile 0 ----
#pragma unroll
    for (int i = 0; i < 4; i++) {
        int f = tid + i * 128;
        int r = f >> 2, kc = (f & 3) * 4;
        As[0][(kc + 0) * ASTR + r] = ra[i].x;
        As[0][(kc + 1) * ASTR + r] = ra[i].y;
        As[0][(kc + 2) * ASTR + r] = ra[i].z;
        As[0][(kc + 3) * ASTR + r] = ra[i].w;
    }
#pragma unroll
    for (int i = 0; i < 2; i++) {
        int f = tid + i * 128;
        if (TRANSB) {
            int r = f >> 2, kc = (f & 3) * 4;
            Bs[0][(kc + 0) * BSTR + r] = rb[i].x;
            Bs[0][(kc + 1) * BSTR + r] = rb[i].y;
            Bs[0][(kc + 2) * BSTR + r] = rb[i].z;
            Bs[0][(kc + 3) * BSTR + r] = rb[i].w;
        } else {
            int k = f >> 4, nn = (f & 15) * 4;
            *(float4*)&Bs[0][k * BSTR + nn] = rb[i];
        }
    }
    __syncthreads();

    const int nk = K / BK;
    for (int kt = 0; kt < nk; kt++) {
        const int buf = kt & 1;
        const int knext = (kt + 1) * BK;
        if (kt + 1 < nk) {
            // prefetch next tile to regs (overlaps with compute)
#pragma unroll
            for (int i = 0; i < 4; i++) {
                int f = tid + i * 128;
                int r = f >> 2, kc = (f & 3) * 4;
                int gm = m0 + r;
                ra[i] = (gm < M) ? *(const float4*)&A[(size_t)gm * lda + knext + kc]
                                 : make_float4(0.f, 0.f, 0.f, 0.f);
            }
#pragma unroll
            for (int i = 0; i < 2; i++) {
                int f = tid + i * 128;
                if (TRANSB) {
                    int r = f >> 2, kc = (f & 3) * 4;
                    rb[i] = *(const float4*)&B[(size_t)(n0 + r) * ldb + knext + kc];
                } else {
                    int k = f >> 4, nn = (f & 15) * 4;
                    rb[i] = *(const float4*)&B[(size_t)(knext + k) * ldb + n0 + nn];
                }
            }
        }
#pragma unroll
        for (int kk = 0; kk < BK; kk++) {
            float4 a0 = *(const float4*)&As[buf][kk * ASTR + tm];
            float4 a1 = *(const float4*)&As[buf][kk * ASTR + tm + 4];
            // b as 4 natural f32x2 pairs (64-bit LDS, same addresses as before)
            const ull* bp = (const ull*)&Bs[buf][kk * BSTR + tn];
            ull b2[4];
            b2[0] = bp[0]; b2[1] = bp[1]; b2[2] = bp[2]; b2[3] = bp[3];
            float av[8] = {a0.x, a0.y, a0.z, a0.w, a1.x, a1.y, a1.z, a1.w};
#pragma unroll
            for (int i = 0; i < 8; i++) {
                ull a2 = pack_dup(av[i]);
#pragma unroll
                for (int j = 0; j < 4; j++)
                    fma_x2(acc[i][j], a2, b2[j]);
            }
        }
        if (kt + 1 < nk) {
            const int nbuf = buf ^ 1;
#pragma unroll
            for (int i = 0; i < 4; i++) {
                int f = tid + i * 128;
                int r = f >> 2, kc = (f & 3) * 4;
                As[nbuf][(kc + 0) * ASTR + r] = ra[i].x;
                As[nbuf][(kc + 1) * ASTR + r] = ra[i].y;
                As[nbuf][(kc + 2) * ASTR + r] = ra[i].z;
                As[nbuf][(kc + 3) * ASTR + r] = ra[i].w;
            }
#pragma unroll
            for (int i = 0; i < 2; i++) {
                int f = tid + i * 128;
                if (TRANSB) {
                    int r = f >> 2, kc = (f & 3) * 4;
                    Bs[nbuf][(kc + 0) * BSTR + r] = rb[i].x;
                    Bs[nbuf][(kc + 1) * BSTR + r] = rb[i].y;
                    Bs[nbuf][(kc + 2) * BSTR + r] = rb[i].z;
                    Bs[nbuf][(kc + 3) * BSTR + r] = rb[i].w;
                } else {
                    int k = f >> 4, nn = (f & 15) * 4;
                    *(float4*)&Bs[nbuf][k * BSTR + nn] = rb[i];
                }
            }
            __syncthreads();
        }
    }

    // ---- epilogue: unpack f32x2 accumulators ----
    float bv[8];
    if (HASBIAS) {
#pragma unroll
        for (int j = 0; j < 8; j++) bv[j] = bias[n0 + tn + j];
    }
#pragma unroll
    for (int i = 0; i < 8; i++) {
        int gm = m0 + tm + i;
        if (gm >= M) continue;
        float2 p0 = *reinterpret_cast<float2*>(&acc[i][0]);
        float2 p1 = *reinterpret_cast<float2*>(&acc[i][1]);
        float2 p2 = *reinterpret_cast<float2*>(&acc[i][2]);
        float2 p3 = *reinterpret_cast<float2*>(&acc[i][3]);
        float4 c0 = make_float4(p0.x, p0.y, p1.x, p1.y);
        float4 c1 = make_float4(p2.x, p2.y, p3.x, p3.y);
        if (HASBIAS) {
            c0.x += bv[0]; c0.y += bv[1]; c0.z += bv[2]; c0.w += bv[3];
            c1.x += bv[4]; c1.y += bv[5]; c1.z += bv[6]; c1.w += bv[7];
        }
        float* crow = &C[(size_t)gm * ldc + n0 + tn];
        *(float4*)&crow[0] = c0;
        *(float4*)&crow[4] = c1;
    }
}

// ---------------- init: h=0, outputs[0]=one-hot(START), x=target[0] ----------------
__global__ void init_kernel(const int* __restrict__ target, float* __restrict__ out)
{
    int i = blockIdx.x * blockDim.x + threadIdx.x;
    if (i < BB * HH) g_h[i] = 0.f;
    if (i < BB * VTGT) out[i] = ((i % VTGT) == STARTTOK) ? 1.f : 0.f;
    if (i < BB) g_x[i] = target[i];
}

// ---------------- build fused decoder weight: [W_hh_dec ; W_attn[:H]^T] ----------------
__global__ void build_wcat(const float* __restrict__ W_hh_dec,
                           const float* __restrict__ W_attn)
{
    int idx = blockIdx.x * blockDim.x + threadIdx.x;
    if (idx >= NCAT * HH) return;
    int n = idx / HH, k = idx - n * HH;
    g_Wcat[idx] = (n < G3H) ? W_hh_dec[idx]
                            : W_attn[(size_t)k * AA + (n - G3H)];
}

// ---------------- encoder GRU cell ----------------
__global__ void gru_enc_cell(const int* __restrict__ source, int s,
                             const float* __restrict__ b_ih,
                             const float* __restrict__ b_hh)
{
    int idx = blockIdx.x * blockDim.x + threadIdx.x;
    if (idx >= BB * HH) return;
    int b = idx / HH, j = idx - b * HH;
    int tok = source[s * BB + b];
    const float* P  = &g_P_enc[(size_t)tok * G3H];
    const float* gh = &g_gh[(size_t)b * G3H];
    float gir = P[j]          + b_ih[j];
    float giz = P[HH + j]     + b_ih[HH + j];
    float gin = P[2 * HH + j] + b_ih[2 * HH + j];
    float ghr = gh[j]          + b_hh[j];
    float ghz = gh[HH + j]     + b_hh[HH + j];
    float ghn = gh[2 * HH + j] + b_hh[2 * HH + j];
    float r = sigmoid_f(gir + ghr);
    float z = sigmoid_f(giz + ghz);
    float n = tanhf(gin + r * ghn);
    float hv = (1.f - z) * n + z * g_h[idx];
    g_h[idx] = hv;
    g_enc_ops[(size_t)s * BB * HH + idx] = hv;
}

// ---------------- decoder GRU cell (gh from fused g_ghp, stride NCAT) ----------------
__global__ void gru_dec_cell(const float* __restrict__ b_ih,
                             const float* __restrict__ b_hh)
{
    int idx = blockIdx.x * blockDim.x + threadIdx.x;
    if (idx >= BB * HH) return;
    int b = idx / HH, j = idx - b * HH;
    int tok = g_x[b];
    const float* P  = &g_P_dec[(size_t)tok * G3H];
    const float* gi = &g_gi[(size_t)b * G3H];
    const float* gh = &g_ghp[(size_t)b * NCAT];
    float gir = gi[j]          + P[j]          + b_ih[j];
    float giz = gi[HH + j]     + P[HH + j]     + b_ih[HH + j];
    float gin = gi[2 * HH + j] + P[2 * HH + j] + b_ih[2 * HH + j];
    float ghr = gh[j]          + b_hh[j];
    float ghz = gh[HH + j]     + b_hh[HH + j];
    float ghn = gh[2 * HH + j] + b_hh[2 * HH + j];
    float r = sigmoid_f(gir + ghr);
    float z = sigmoid_f(giz + ghz);
    float n = tanhf(gin + r * ghn);
    g_h[idx] = (1.f - z) * n + z * g_h[idx];
}

// ---------------- fused attention: scores -> softmax -> context ----------------
// One block per batch element b; 1024 threads (32 warps). Warp w owns source pos s=w.
__global__ __launch_bounds__(1024)
void attn_fused_kernel(const float* __restrict__ v_attn,
                       float* __restrict__ attn_plane /* (B,S) */)
{
    int b = blockIdx.x;
    int tid = threadIdx.x;
    int w = tid >> 5, lane = tid & 31;

    __shared__ float hp_s[AA];
    __shared__ float v_s[AA];
    __shared__ float sc[SS];
    __shared__ float alpha_s[SS];

    hp_s[tid] = g_ghp[(size_t)b * NCAT + G3H + tid];   // hproj lives after gh
    v_s[tid]  = v_attn[tid];
    __syncthreads();

    // score[s=w] = sum_a tanh(enc_proj[s,b,a] + hproj[b,a]) * v[a]
    const float* ep = &g_enc_proj[((size_t)w * BB + b) * AA];
    float sum = 0.f;
#pragma unroll
    for (int i = 0; i < AA / 32; i++) {
        int a = i * 32 + lane;
        sum += tanh_fast(ep[a] + hp_s[a]) * v_s[a];
    }
#pragma unroll
    for (int off = 16; off > 0; off >>= 1)
        sum += __shfl_xor_sync(0xffffffffu, sum, off);
    if (lane == 0) sc[w] = sum;
    __syncthreads();

    // softmax over s (warp 0, lane = s)
    if (w == 0) {
        float v = sc[lane];
        float mx = v;
#pragma unroll
        for (int off = 16; off > 0; off >>= 1)
            mx = fmaxf(mx, __shfl_xor_sync(0xffffffffu, mx, off));
        float e = __expf(v - mx);
        float ssum = e;
#pragma unroll
        for (int off = 16; off > 0; off >>= 1)
            ssum += __shfl_xor_sync(0xffffffffu, ssum, off);
        float al = e / ssum;
        alpha_s[lane] = al;
        attn_plane[b * SS + lane] = al;
    }
    __syncthreads();

    // ctx[b,h] = sum_s alpha[s] * enc_ops[s,b,h]   (tid = h)
    float accv = 0.f;
#pragma unroll
    for (int s = 0; s < SS; s++)
        accv = fmaf(alpha_s[s], g_enc_ops[((size_t)s * BB + b) * HH + tid], accv);
    g_ctx[(size_t)b * HH + tid] = accv;
}

// ---------------- logits + next-token (teacher forcing or argmax) ----------------
__global__ void logits_kernel(const float* __restrict__ W_out,  // (H, VT) row-major
                              const float* __restrict__ b_out,
                              const int* __restrict__ target,
                              const int* __restrict__ tf_ptr,
                              int t, float* __restrict__ out)
{
    int b = blockIdx.x;
    __shared__ float hs[HH];
    for (int k = threadIdx.x; k < HH; k += 128) hs[k] = g_h[(size_t)b * HH + k];
    __syncthreads();
    int v = threadIdx.x;
    float lg = -1e30f;
    if (v < VTGT) {
        float acc = b_out[v];
#pragma unroll 8
        for (int k = 0; k < HH; k++) acc = fmaf(hs[k], W_out[k * VTGT + v], acc);
        out[(size_t)t * BB * VTGT + (size_t)b * VTGT + v] = acc;
        lg = acc;
    }
    __shared__ float sv[128];
    __shared__ int   si[128];
    sv[threadIdx.x] = lg;
    si[threadIdx.x] = v;
    __syncthreads();
#pragma unroll
    for (int off = 64; off > 0; off >>= 1) {
        if (threadIdx.x < off) {
            float vo = sv[threadIdx.x + off];
            int   io = si[threadIdx.x + off];
            if (vo > sv[threadIdx.x] || (vo == sv[threadIdx.x] && io < si[threadIdx.x])) {
                sv[threadIdx.x] = vo;
                si[threadIdx.x] = io;
            }
        }
        __syncthreads();
    }
    if (threadIdx.x == 0)
        g_x[b] = (*tf_ptr != 0) ? target[t * BB + b] : si[0];
}

// ---------------- host-side orchestration ----------------
static inline void gemm(const float* A, int lda, const float* B, int ldb,
                        const float* bias, float* C, int ldc,
                        int M, int N, int K, bool transB)
{
    dim3 grid(N / BN, (M + BM - 1) / BM);
    if (transB)
        sgemm_kernel<true, false><<<grid, 128>>>(A, lda, B, ldb, nullptr, C, ldc, M, N, K);
    else if (bias)
        sgemm_kernel<false, true><<<grid, 128>>>(A, lda, B, ldb, bias, C, ldc, M, N, K);
    else
        sgemm_kernel<false, false><<<grid, 128>>>(A, lda, B, ldb, nullptr, C, ldc, M, N, K);
}

extern "C" void kernel_launch(void* const* d_in, const int* in_sizes, int n_in,
                              void* d_out, int out_size)
{
    const int*   source   = (const int*)  d_in[0];
    const int*   target   = (const int*)  d_in[1];
    const int*   tf       = (const int*)  d_in[2];
    const float* emb_src  = (const float*)d_in[3];
    const float* W_ih_enc = (const float*)d_in[4];
    const float* W_hh_enc = (const float*)d_in[5];
    const float* b_ih_enc = (const float*)d_in[6];
    const float* b_hh_enc = (const float*)d_in[7];
    const float* emb_tgt  = (const float*)d_in[8];
    const float* W_attn   = (const float*)d_in[9];
    const float* b_attn   = (const float*)d_in[10];
    const float* v_attn   = (const float*)d_in[11];
    const float* W_ih_dec = (const float*)d_in[12];
    const float* W_hh_dec = (const float*)d_in[13];
    const float* b_ih_dec = (const float*)d_in[14];
    const float* b_hh_dec = (const float*)d_in[15];
    const float* W_out    = (const float*)d_in[16];
    const float* b_out    = (const float*)d_in[17];

    float* out      = (float*)d_out;
    float* attn_out = out + (size_t)TT * BB * VTGT;

    float *pP_enc, *pP_dec, *ph, *penc, *pproj, *pgh, *pghp, *pgi, *pctx, *pWcat;
    cudaGetSymbolAddress((void**)&pP_enc, g_P_enc);
    cudaGetSymbolAddress((void**)&pP_dec, g_P_dec);
    cudaGetSymbolAddress((void**)&ph,     g_h);
    cudaGetSymbolAddress((void**)&penc,   g_enc_ops);
    cudaGetSymbolAddress((void**)&pproj,  g_enc_proj);
    cudaGetSymbolAddress((void**)&pgh,    g_gh);
    cudaGetSymbolAddress((void**)&pghp,   g_ghp);
    cudaGetSymbolAddress((void**)&pgi,    g_gi);
    cudaGetSymbolAddress((void**)&pctx,   g_ctx);
    cudaGetSymbolAddress((void**)&pWcat,  g_Wcat);

    // init: h=0, outputs row 0, x = target[0]
    init_kernel<<<(BB * HH + 255) / 256, 256>>>(target, out);

    // token-projection tables (fold embedding gather through the input GEMMs)
    gemm(emb_src, EE, W_ih_enc, EE, nullptr, pP_enc, G3H, VSRC, G3H, EE, true);
    gemm(emb_tgt, EE, W_ih_dec + HH, HH + EE, nullptr, pP_dec, G3H, VTGT, G3H, EE, true);

    // fused decoder weight [W_hh_dec ; W_attn[:H]^T]
    build_wcat<<<(NCAT * HH + 255) / 256, 256>>>(W_hh_dec, W_attn);

    // ---------------- encoder ----------------
    for (int s = 0; s < SS; s++) {
        gemm(ph, HH, W_hh_enc, HH, nullptr, pgh, G3H, BB, G3H, HH, true);
        gru_enc_cell<<<(BB * HH + 255) / 256, 256>>>(source, s, b_ih_enc, b_hh_enc);
    }

    // step-invariant half of the attention energy (+ bias folded in)
    gemm(penc, HH, W_attn + (size_t)HH * AA, AA, b_attn, pproj, AA, SS * BB, AA, HH, false);

    // ---------------- decoder ----------------
    for (int t = 1; t < TT; t++) {
        // one fused GEMM: h -> [gh (3072) | hproj (1024)]
        gemm(ph, HH, pWcat, HH, nullptr, pghp, NCAT, BB, NCAT, HH, true);
        attn_fused_kernel<<<BB, 1024>>>(v_attn, attn_out + (size_t)(t - 1) * BB * SS);
        gemm(pctx, HH, W_ih_dec, HH + EE, nullptr, pgi, G3H, BB, G3H, HH, true);
        gru_dec_cell<<<(BB * HH + 255) / 256, 256>>>(b_ih_dec, b_hh_dec);
        logits_kernel<<<BB, 128>>>(W_out, b_out, target, tf, t, out);
    }
}

// round 6
// speedup vs baseline: 5.9680x; 1.7284x over previous
#include <cuda_runtime.h>
#include <cuda_bf16.h>

// ---------------- problem constants ----------------
#define SS   32      // source length
#define TT   32      // target length
#define BB   512     // batch
#define HH   1024    // hidden
#define EE   256     // embed
#define AA   1024    // attention dim
#define VSRC 64
#define VTGT 70
#define G3H  3072    // 3*H
#define NCAT 4096    // 3H (gh) + A (hproj) fused decoder GEMM width
#define STARTTOK 1

typedef unsigned long long ull;
typedef __nv_bfloat16 bf16;

// ---------------- scratch (__device__ globals; no allocation) ----------------
__device__ float g_P_enc[VSRC * G3H];        // emb_src @ W_ih_enc^T
__device__ float g_P_dec[VTGT * G3H];        // emb_tgt @ W_ih_dec[:,H:]^T
__device__ float g_Wcat[NCAT * HH];          // [W_hh_dec ; W_attn[:H]^T] (n,k) layout
__device__ float g_h[BB * HH];               // recurrent hidden state
__device__ float g_enc_ops[SS * BB * HH];    // encoder outputs         (67MB)
__device__ float g_enc_proj[SS * BB * AA];   // enc_ops@W_attn[H:]+b    (67MB)
__device__ float g_gh[BB * G3H];             // encoder: h @ W_hh_enc^T
__device__ float g_ghp[BB * NCAT];           // decoder: h @ Wcat^T  (gh | hproj)
__device__ float g_gi[BB * G3H];             // ctx @ W_ih_dec[:, :H]^T
__device__ float g_ctx[BB * HH];
__device__ int   g_x[BB];                    // decoder input token

// split-bf16 weight copies (hi + lo), all packed (N, K=1024)
__device__ bf16 g_Whe_hi[G3H * HH],  g_Whe_lo[G3H * HH];   // W_hh_enc
__device__ bf16 g_Wct_hi[NCAT * HH], g_Wct_lo[NCAT * HH];  // Wcat
__device__ bf16 g_Wid_hi[G3H * HH],  g_Wid_lo[G3H * HH];   // W_ih_dec[:, :H]
__device__ bf16 g_Wa2_hi[AA * HH],   g_Wa2_lo[AA * HH];    // W_attn[H:]^T

__device__ __forceinline__ float tanh_fast(float x) {
    float y;
    asm("tanh.approx.f32 %0, %1;" : "=f"(y) : "f"(x));
    return y;
}
__device__ __forceinline__ float sigmoid_f(float x) {
    return 1.f / (1.f + __expf(-x));
}
// pack two f32 -> bf16x2 (low half = lo arg, high half = hi arg)
__device__ __forceinline__ unsigned pack_bf2(float lo, float hi) {
    unsigned r;
    asm("cvt.rn.bf16x2.f32 %0, %1, %2;" : "=r"(r) : "f"(hi), "f"(lo));
    return r;
}
__device__ __forceinline__ void mma16816(float* c, const unsigned* a, const unsigned* b) {
    asm volatile(
        "mma.sync.aligned.m16n8k16.row.col.f32.bf16.bf16.f32 "
        "{%0,%1,%2,%3}, {%4,%5,%6,%7}, {%8,%9}, {%0,%1,%2,%3};"
        : "+f"(c[0]), "+f"(c[1]), "+f"(c[2]), "+f"(c[3])
        : "r"(a[0]), "r"(a[1]), "r"(a[2]), "r"(a[3]), "r"(b[0]), "r"(b[1]));
}

// ============== split-bf16 tensor-core GEMM ==============
// C[M,N] = A[M,K](f32) @ B^T, B given as bf16 hi/lo (N,K) packed.
// Requires M%64==0, N%64==0, K%32==0.
#define GBM 64
#define GBN 64
#define GBK 32
#define SSTR 40   // smem row stride in bf16 elems (80B) -> conflict-free frags

template<bool HASBIAS>
__global__ __launch_bounds__(128)
void gemm_bf16x3_kernel(const float* __restrict__ A, int lda,
                        const bf16* __restrict__ Bhi,
                        const bf16* __restrict__ Blo,
                        const float* __restrict__ bias,
                        float* __restrict__ C, int ldc,
                        int M, int N, int K)
{
    __shared__ __align__(16) bf16 Ah[GBM * SSTR];
    __shared__ __align__(16) bf16 Al[GBM * SSTR];
    __shared__ __align__(16) bf16 Bh[GBN * SSTR];
    __shared__ __align__(16) bf16 Bl[GBN * SSTR];

    const int tid  = threadIdx.x;
    const int w    = tid >> 5;          // warp 0..3 -> n slice [w*16, w*16+16)
    const int lane = tid & 31;
    const int g    = lane >> 2;         // 0..7
    const int tig  = lane & 3;          // 0..3
    const int m0   = blockIdx.y * GBM;
    const int n0   = blockIdx.x * GBN;

    float acc[4][2][4];
#pragma unroll
    for (int mt = 0; mt < 4; mt++)
#pragma unroll
        for (int nt = 0; nt < 2; nt++)
#pragma unroll
            for (int c = 0; c < 4; c++) acc[mt][nt][c] = 0.f;

    for (int k0 = 0; k0 < K; k0 += GBK) {
        // ---- stage A tile (64x32 f32 -> hi/lo bf16) ----
#pragma unroll
        for (int i = 0; i < 4; i++) {
            int f = tid + i * 128;          // float4 slot in 64x8 grid
            int r = f >> 3, c4 = (f & 7) * 4;
            float4 v = *(const float4*)&A[(size_t)(m0 + r) * lda + k0 + c4];
            unsigned ph01 = pack_bf2(v.x, v.y);
            unsigned ph23 = pack_bf2(v.z, v.w);
            float rx = v.x - __uint_as_float(ph01 << 16);
            float ry = v.y - __uint_as_float(ph01 & 0xffff0000u);
            float rz = v.z - __uint_as_float(ph23 << 16);
            float rw = v.w - __uint_as_float(ph23 & 0xffff0000u);
            unsigned pl01 = pack_bf2(rx, ry);
            unsigned pl23 = pack_bf2(rz, rw);
            *(uint2*)&Ah[r * SSTR + c4] = make_uint2(ph01, ph23);
            *(uint2*)&Al[r * SSTR + c4] = make_uint2(pl01, pl23);
        }
        // ---- stage B tile (64x32 bf16 hi + lo) ----
#pragma unroll
        for (int i = 0; i < 4; i++) {
            int f = tid + i * 128;
            int r = f >> 3, c4 = (f & 7) * 4;
            size_t goff = (size_t)(n0 + r) * K + k0 + c4;
            *(uint2*)&Bh[r * SSTR + c4] = *(const uint2*)&Bhi[goff];
            *(uint2*)&Bl[r * SSTR + c4] = *(const uint2*)&Blo[goff];
        }
        __syncthreads();

#pragma unroll
        for (int kk = 0; kk < GBK; kk += 16) {
            unsigned ah[4][4], al[4][4], bh[2][2], bl[2][2];
#pragma unroll
            for (int mt = 0; mt < 4; mt++) {
                int r0 = mt * 16 + g;
                ah[mt][0] = *(const unsigned*)&Ah[(r0    ) * SSTR + kk +     tig * 2];
                ah[mt][1] = *(const unsigned*)&Ah[(r0 + 8) * SSTR + kk +     tig * 2];
                ah[mt][2] = *(const unsigned*)&Ah[(r0    ) * SSTR + kk + 8 + tig * 2];
                ah[mt][3] = *(const unsigned*)&Ah[(r0 + 8) * SSTR + kk + 8 + tig * 2];
                al[mt][0] = *(const unsigned*)&Al[(r0    ) * SSTR + kk +     tig * 2];
                al[mt][1] = *(const unsigned*)&Al[(r0 + 8) * SSTR + kk +     tig * 2];
                al[mt][2] = *(const unsigned*)&Al[(r0    ) * SSTR + kk + 8 + tig * 2];
                al[mt][3] = *(const unsigned*)&Al[(r0 + 8) * SSTR + kk + 8 + tig * 2];
            }
#pragma unroll
            for (int nt = 0; nt < 2; nt++) {
                int nb = w * 16 + nt * 8 + g;
                bh[nt][0] = *(const unsigned*)&Bh[nb * SSTR + kk +     tig * 2];
                bh[nt][1] = *(const unsigned*)&Bh[nb * SSTR + kk + 8 + tig * 2];
                bl[nt][0] = *(const unsigned*)&Bl[nb * SSTR + kk +     tig * 2];
                bl[nt][1] = *(const unsigned*)&Bl[nb * SSTR + kk + 8 + tig * 2];
            }
#pragma unroll
            for (int mt = 0; mt < 4; mt++)
#pragma unroll
                for (int nt = 0; nt < 2; nt++) {
                    mma16816(acc[mt][nt], ah[mt], bh[nt]);   // hi*hi
                    mma16816(acc[mt][nt], ah[mt], bl[nt]);   // hi*lo
                    mma16816(acc[mt][nt], al[mt], bh[nt]);   // lo*hi
                }
        }
        __syncthreads();
    }

    // ---- epilogue ----
#pragma unroll
    for (int mt = 0; mt < 4; mt++) {
#pragma unroll
        for (int nt = 0; nt < 2; nt++) {
            int gm = m0 + mt * 16 + g;
            int gn = n0 + w * 16 + nt * 8 + tig * 2;
            float b0 = 0.f, b1 = 0.f;
            if (HASBIAS) { b0 = bias[gn]; b1 = bias[gn + 1]; }
            float2 v0 = make_float2(acc[mt][nt][0] + b0, acc[mt][nt][1] + b1);
            float2 v1 = make_float2(acc[mt][nt][2] + b0, acc[mt][nt][3] + b1);
            *(float2*)&C[(size_t)gm * ldc + gn]       = v0;
            *(float2*)&C[(size_t)(gm + 8) * ldc + gn] = v1;
        }
    }
}

// ---------------- weight conversion: f32 -> bf16 hi/lo ----------------
// (N,K) row-major source with row stride ld
__global__ void conv_nk(const float* __restrict__ W, int ld,
                        bf16* __restrict__ hi, bf16* __restrict__ lo,
                        int Nn, int Kk)
{
    int idx = blockIdx.x * blockDim.x + threadIdx.x;
    if (idx >= Nn * Kk) return;
    int n = idx / Kk, k = idx - n * Kk;
    float x = W[(size_t)n * ld + k];
    bf16 h = __float2bfloat16(x);
    hi[idx] = h;
    lo[idx] = __float2bfloat16(x - __bfloat162float(h));
}
// transposed source: out[n][k] = W[k*ld + n]
__global__ void conv_kn(const float* __restrict__ W, int ld,
                        bf16* __restrict__ hi, bf16* __restrict__ lo,
                        int Nn, int Kk)
{
    int idx = blockIdx.x * blockDim.x + threadIdx.x;
    if (idx >= Nn * Kk) return;
    int n = idx / Kk, k = idx - n * Kk;
    float x = W[(size_t)k * ld + n];
    bf16 h = __float2bfloat16(x);
    hi[idx] = h;
    lo[idx] = __float2bfloat16(x - __bfloat162float(h));
}

// ---------------- fp32 SGEMM (kept for tiny one-time precompute GEMMs) ----------------
#define BM 128
#define BN 64
#define BK 16
#define ASTR (BM + 4)
#define BSTR (BN + 4)

__global__ __launch_bounds__(128)
void sgemm_tb_kernel(const float* __restrict__ A, int lda,
                     const float* __restrict__ B, int ldb,
                     float* __restrict__ C, int ldc,
                     int M, int N, int K)
{
    __shared__ float As[BK * ASTR];
    __shared__ float Bs[BK * BSTR];
    const int tid = threadIdx.x;
    const int m0 = blockIdx.y * BM;
    const int n0 = blockIdx.x * BN;
    const int tm = (tid >> 3) * 8;
    const int tn = (tid & 7) * 8;

    float acc[8][8];
#pragma unroll
    for (int i = 0; i < 8; i++)
#pragma unroll
        for (int j = 0; j < 8; j++) acc[i][j] = 0.f;

    for (int k0 = 0; k0 < K; k0 += BK) {
#pragma unroll
        for (int i = 0; i < 4; i++) {
            int f = tid + i * 128;
            int r = f >> 2, kc = (f & 3) * 4;
            int gm = m0 + r;
            float4 v = (gm < M) ? *(const float4*)&A[(size_t)gm * lda + k0 + kc]
                                : make_float4(0.f, 0.f, 0.f, 0.f);
            As[(kc + 0) * ASTR + r] = v.x;
            As[(kc + 1) * ASTR + r] = v.y;
            As[(kc + 2) * ASTR + r] = v.z;
            As[(kc + 3) * ASTR + r] = v.w;
        }
#pragma unroll
        for (int i = 0; i < 2; i++) {
            int f = tid + i * 128;
            int r = f >> 2, kc = (f & 3) * 4;
            float4 v = *(const float4*)&B[(size_t)(n0 + r) * ldb + k0 + kc];
            Bs[(kc + 0) * BSTR + r] = v.x;
            Bs[(kc + 1) * BSTR + r] = v.y;
            Bs[(kc + 2) * BSTR + r] = v.z;
            Bs[(kc + 3) * BSTR + r] = v.w;
        }
        __syncthreads();
#pragma unroll
        for (int kk = 0; kk < BK; kk++) {
            float av[8], bv[8];
#pragma unroll
            for (int i = 0; i < 4; i++) ((float2*)av)[i] = *(float2*)&As[kk * ASTR + tm + i * 2];
#pragma unroll
            for (int j = 0; j < 4; j++) ((float2*)bv)[j] = *(float2*)&Bs[kk * BSTR + tn + j * 2];
#pragma unroll
            for (int i = 0; i < 8; i++)
#pragma unroll
                for (int j = 0; j < 8; j++)
                    acc[i][j] = fmaf(av[i], bv[j], acc[i][j]);
        }
        __syncthreads();
    }
#pragma unroll
    for (int i = 0; i < 8; i++) {
        int gm = m0 + tm + i;
        if (gm >= M) continue;
        float* crow = &C[(size_t)gm * ldc + n0 + tn];
#pragma unroll
        for (int j = 0; j < 8; j++) crow[j] = acc[i][j];
    }
}

// ---------------- init ----------------
__global__ void init_kernel(const int* __restrict__ target, float* __restrict__ out)
{
    int i = blockIdx.x * blockDim.x + threadIdx.x;
    if (i < BB * HH) g_h[i] = 0.f;
    if (i < BB * VTGT) out[i] = ((i % VTGT) == STARTTOK) ? 1.f : 0.f;
    if (i < BB) g_x[i] = target[i];
}

// ---------------- build fused decoder weight: [W_hh_dec ; W_attn[:H]^T] ----------------
__global__ void build_wcat(const float* __restrict__ W_hh_dec,
                           const float* __restrict__ W_attn)
{
    int idx = blockIdx.x * blockDim.x + threadIdx.x;
    if (idx >= NCAT * HH) return;
    int n = idx / HH, k = idx - n * HH;
    g_Wcat[idx] = (n < G3H) ? W_hh_dec[idx]
                            : W_attn[(size_t)k * AA + (n - G3H)];
}

// ---------------- encoder GRU cell ----------------
__global__ void gru_enc_cell(const int* __restrict__ source, int s,
                             const float* __restrict__ b_ih,
                             const float* __restrict__ b_hh)
{
    int idx = blockIdx.x * blockDim.x + threadIdx.x;
    if (idx >= BB * HH) return;
    int b = idx / HH, j = idx - b * HH;
    int tok = source[s * BB + b];
    const float* P  = &g_P_enc[(size_t)tok * G3H];
    const float* gh = &g_gh[(size_t)b * G3H];
    float gir = P[j]          + b_ih[j];
    float giz = P[HH + j]     + b_ih[HH + j];
    float gin = P[2 * HH + j] + b_ih[2 * HH + j];
    float ghr = gh[j]          + b_hh[j];
    float ghz = gh[HH + j]     + b_hh[HH + j];
    float ghn = gh[2 * HH + j] + b_hh[2 * HH + j];
    float r = sigmoid_f(gir + ghr);
    float z = sigmoid_f(giz + ghz);
    float n = tanhf(gin + r * ghn);
    float hv = (1.f - z) * n + z * g_h[idx];
    g_h[idx] = hv;
    g_enc_ops[(size_t)s * BB * HH + idx] = hv;
}

// ---------------- decoder GRU cell ----------------
__global__ void gru_dec_cell(const float* __restrict__ b_ih,
                             const float* __restrict__ b_hh)
{
    int idx = blockIdx.x * blockDim.x + threadIdx.x;
    if (idx >= BB * HH) return;
    int b = idx / HH, j = idx - b * HH;
    int tok = g_x[b];
    const float* P  = &g_P_dec[(size_t)tok * G3H];
    const float* gi = &g_gi[(size_t)b * G3H];
    const float* gh = &g_ghp[(size_t)b * NCAT];
    float gir = gi[j]          + P[j]          + b_ih[j];
    float giz = gi[HH + j]     + P[HH + j]     + b_ih[HH + j];
    float gin = gi[2 * HH + j] + P[2 * HH + j] + b_ih[2 * HH + j];
    float ghr = gh[j]          + b_hh[j];
    float ghz = gh[HH + j]     + b_hh[HH + j];
    float ghn = gh[2 * HH + j] + b_hh[2 * HH + j];
    float r = sigmoid_f(gir + ghr);
    float z = sigmoid_f(giz + ghz);
    float n = tanhf(gin + r * ghn);
    g_h[idx] = (1.f - z) * n + z * g_h[idx];
}

// ---------------- fused attention: scores -> softmax -> context ----------------
__global__ __launch_bounds__(1024)
void attn_fused_kernel(const float* __restrict__ v_attn,
                       float* __restrict__ attn_plane /* (B,S) */)
{
    int b = blockIdx.x;
    int tid = threadIdx.x;
    int w = tid >> 5, lane = tid & 31;

    __shared__ float hp_s[AA];
    __shared__ float v_s[AA];
    __shared__ float sc[SS];
    __shared__ float alpha_s[SS];

    hp_s[tid] = g_ghp[(size_t)b * NCAT + G3H + tid];
    v_s[tid]  = v_attn[tid];
    __syncthreads();

    const float* ep = &g_enc_proj[((size_t)w * BB + b) * AA];
    float sum = 0.f;
#pragma unroll
    for (int i = 0; i < AA / 32; i++) {
        int a = i * 32 + lane;
        sum += tanh_fast(ep[a] + hp_s[a]) * v_s[a];
    }
#pragma unroll
    for (int off = 16; off > 0; off >>= 1)
        sum += __shfl_xor_sync(0xffffffffu, sum, off);
    if (lane == 0) sc[w] = sum;
    __syncthreads();

    if (w == 0) {
        float v = sc[lane];
        float mx = v;
#pragma unroll
        for (int off = 16; off > 0; off >>= 1)
            mx = fmaxf(mx, __shfl_xor_sync(0xffffffffu, mx, off));
        float e = __expf(v - mx);
        float ssum = e;
#pragma unroll
        for (int off = 16; off > 0; off >>= 1)
            ssum += __shfl_xor_sync(0xffffffffu, ssum, off);
        float al = e / ssum;
        alpha_s[lane] = al;
        attn_plane[b * SS + lane] = al;
    }
    __syncthreads();

    float accv = 0.f;
#pragma unroll
    for (int s = 0; s < SS; s++)
        accv = fmaf(alpha_s[s], g_enc_ops[((size_t)s * BB + b) * HH + tid], accv);
    g_ctx[(size_t)b * HH + tid] = accv;
}

// ---------------- logits + next-token ----------------
__global__ void logits_kernel(const float* __restrict__ W_out,
                              const float* __restrict__ b_out,
                              const int* __restrict__ target,
                              const int* __restrict__ tf_ptr,
                              int t, float* __restrict__ out)
{
    int b = blockIdx.x;
    __shared__ float hs[HH];
    for (int k = threadIdx.x; k < HH; k += 128) hs[k] = g_h[(size_t)b * HH + k];
    __syncthreads();
    int v = threadIdx.x;
    float lg = -1e30f;
    if (v < VTGT) {
        float acc = b_out[v];
#pragma unroll 8
        for (int k = 0; k < HH; k++) acc = fmaf(hs[k], W_out[k * VTGT + v], acc);
        out[(size_t)t * BB * VTGT + (size_t)b * VTGT + v] = acc;
        lg = acc;
    }
    __shared__ float sv[128];
    __shared__ int   si[128];
    sv[threadIdx.x] = lg;
    si[threadIdx.x] = v;
    __syncthreads();
#pragma unroll
    for (int off = 64; off > 0; off >>= 1) {
        if (threadIdx.x < off) {
            float vo = sv[threadIdx.x + off];
            int   io = si[threadIdx.x + off];
            if (vo > sv[threadIdx.x] || (vo == sv[threadIdx.x] && io < si[threadIdx.x])) {
                sv[threadIdx.x] = vo;
                si[threadIdx.x] = io;
            }
        }
        __syncthreads();
    }
    if (threadIdx.x == 0)
        g_x[b] = (*tf_ptr != 0) ? target[t * BB + b] : si[0];
}

// ---------------- host-side orchestration ----------------
static inline void gemm_tc(const float* A, int lda, const bf16* Bhi, const bf16* Blo,
                           const float* bias, float* C, int ldc, int M, int N, int K)
{
    dim3 grid(N / GBN, M / GBM);
    if (bias)
        gemm_bf16x3_kernel<true><<<grid, 128>>>(A, lda, Bhi, Blo, bias, C, ldc, M, N, K);
    else
        gemm_bf16x3_kernel<false><<<grid, 128>>>(A, lda, Bhi, Blo, nullptr, C, ldc, M, N, K);
}

extern "C" void kernel_launch(void* const* d_in, const int* in_sizes, int n_in,
                              void* d_out, int out_size)
{
    const int*   source   = (const int*)  d_in[0];
    const int*   target   = (const int*)  d_in[1];
    const int*   tf       = (const int*)  d_in[2];
    const float* emb_src  = (const float*)d_in[3];
    const float* W_ih_enc = (const float*)d_in[4];
    const float* W_hh_enc = (const float*)d_in[5];
    const float* b_ih_enc = (const float*)d_in[6];
    const float* b_hh_enc = (const float*)d_in[7];
    const float* emb_tgt  = (const float*)d_in[8];
    const float* W_attn   = (const float*)d_in[9];
    const float* b_attn   = (const float*)d_in[10];
    const float* v_attn   = (const float*)d_in[11];
    const float* W_ih_dec = (const float*)d_in[12];
    const float* W_hh_dec = (const float*)d_in[13];
    const float* b_ih_dec = (const float*)d_in[14];
    const float* b_hh_dec = (const float*)d_in[15];
    const float* W_out    = (const float*)d_in[16];
    const float* b_out    = (const float*)d_in[17];

    float* out      = (float*)d_out;
    float* attn_out = out + (size_t)TT * BB * VTGT;

    float *pP_enc, *pP_dec, *ph, *penc, *pproj, *pgh, *pghp, *pgi, *pctx, *pWcat;
    cudaGetSymbolAddress((void**)&pP_enc, g_P_enc);
    cudaGetSymbolAddress((void**)&pP_dec, g_P_dec);
    cudaGetSymbolAddress((void**)&ph,     g_h);
    cudaGetSymbolAddress((void**)&penc,   g_enc_ops);
    cudaGetSymbolAddress((void**)&pproj,  g_enc_proj);
    cudaGetSymbolAddress((void**)&pgh,    g_gh);
    cudaGetSymbolAddress((void**)&pghp,   g_ghp);
    cudaGetSymbolAddress((void**)&pgi,    g_gi);
    cudaGetSymbolAddress((void**)&pctx,   g_ctx);
    cudaGetSymbolAddress((void**)&pWcat,  g_Wcat);

    bf16 *pWhe_h, *pWhe_l, *pWct_h, *pWct_l, *pWid_h, *pWid_l, *pWa2_h, *pWa2_l;
    cudaGetSymbolAddress((void**)&pWhe_h, g_Whe_hi);
    cudaGetSymbolAddress((void**)&pWhe_l, g_Whe_lo);
    cudaGetSymbolAddress((void**)&pWct_h, g_Wct_hi);
    cudaGetSymbolAddress((void**)&pWct_l, g_Wct_lo);
    cudaGetSymbolAddress((void**)&pWid_h, g_Wid_hi);
    cudaGetSymbolAddress((void**)&pWid_l, g_Wid_lo);
    cudaGetSymbolAddress((void**)&pWa2_h, g_Wa2_hi);
    cudaGetSymbolAddress((void**)&pWa2_l, g_Wa2_lo);

    // init: h=0, outputs row 0, x = target[0]
    init_kernel<<<(BB * HH + 255) / 256, 256>>>(target, out);

    // token-projection tables (fold embedding gather through the input GEMMs)
    {
        dim3 g1(G3H / BN, (VSRC + BM - 1) / BM);
        sgemm_tb_kernel<<<g1, 128>>>(emb_src, EE, W_ih_enc, EE, pP_enc, G3H, VSRC, G3H, EE);
        dim3 g2(G3H / BN, (VTGT + BM - 1) / BM);
        sgemm_tb_kernel<<<g2, 128>>>(emb_tgt, EE, W_ih_dec + HH, HH + EE, pP_dec, G3H, VTGT, G3H, EE);
    }

    // fused decoder weight + all split-bf16 weight conversions (one-time)
    build_wcat<<<(NCAT * HH + 255) / 256, 256>>>(W_hh_dec, W_attn);
    conv_nk<<<(G3H  * HH + 255) / 256, 256>>>(W_hh_enc, HH,       pWhe_h, pWhe_l, G3H,  HH);
    conv_nk<<<(NCAT * HH + 255) / 256, 256>>>(pWcat,    HH,       pWct_h, pWct_l, NCAT, HH);
    conv_nk<<<(G3H  * HH + 255) / 256, 256>>>(W_ih_dec, HH + EE,  pWid_h, pWid_l, G3H,  HH);
    conv_kn<<<(AA   * HH + 255) / 256, 256>>>(W_attn + (size_t)HH * AA, AA, pWa2_h, pWa2_l, AA, HH);

    // ---------------- encoder ----------------
    for (int s = 0; s < SS; s++) {
        gemm_tc(ph, HH, pWhe_h, pWhe_l, nullptr, pgh, G3H, BB, G3H, HH);
        gru_enc_cell<<<(BB * HH + 255) / 256, 256>>>(source, s, b_ih_enc, b_hh_enc);
    }

    // step-invariant half of attention energy (+ bias folded in)
    gemm_tc(penc, HH, pWa2_h, pWa2_l, b_attn, pproj, AA, SS * BB, AA, HH);

    // ---------------- decoder ----------------
    for (int t = 1; t < TT; t++) {
        gemm_tc(ph, HH, pWct_h, pWct_l, nullptr, pghp, NCAT, BB, NCAT, HH);
        attn_fused_kernel<<<BB, 1024>>>(v_attn, attn_out + (size_t)(t - 1) * BB * SS);
        gemm_tc(pctx, HH, pWid_h, pWid_l, nullptr, pgi, G3H, BB, G3H, HH);
        gru_dec_cell<<<(BB * HH + 255) / 256, 256>>>(b_ih_dec, b_hh_dec);
        logits_kernel<<<BB, 128>>>(W_out, b_out, target, tf, t, out);
    }
}

// round 7
// speedup vs baseline: 6.0383x; 1.0118x over previous
#include <cuda_runtime.h>
#include <cuda_bf16.h>

// ---------------- problem constants ----------------
#define SS   32      // source length
#define TT   32      // target length
#define BB   512     // batch
#define HH   1024    // hidden
#define EE   256     // embed
#define AA   1024    // attention dim
#define VSRC 64
#define VTGT 70
#define G3H  3072    // 3*H
#define NCAT 4096    // 3H (gh) + A (hproj) fused decoder GEMM width
#define STARTTOK 1

typedef __nv_bfloat16 bf16;

// ---------------- scratch (__device__ globals; no allocation) ----------------
__device__ float g_P_enc[VSRC * G3H];
__device__ float g_P_dec[VTGT * G3H];
__device__ float g_h[BB * HH];
__device__ __align__(16) bf16 g_h_hi[BB * HH], g_h_lo[BB * HH];
__device__ float g_enc_ops[SS * BB * HH];                         // f32 (ctx gather)
__device__ __align__(16) bf16 g_enc_hi[SS * BB * HH], g_enc_lo[SS * BB * HH];
__device__ float g_enc_proj[SS * BB * AA];
__device__ float g_ghp[BB * NCAT];           // decoder: h @ Wcat^T  (gh | hproj)
__device__ float g_gh[BB * G3H];             // encoder: h @ W_hh_enc^T
__device__ float g_gi[BB * G3H];             // ctx @ W_ih_dec[:, :H]^T
__device__ float g_ctx[BB * HH];
__device__ __align__(16) bf16 g_ctx_hi[BB * HH], g_ctx_lo[BB * HH];
__device__ int   g_x[BB];

// split-bf16 weights (hi + lo), packed (N, K=1024)
__device__ __align__(16) bf16 g_Whe_hi[G3H * HH],  g_Whe_lo[G3H * HH];   // W_hh_enc
__device__ __align__(16) bf16 g_Wct_hi[NCAT * HH], g_Wct_lo[NCAT * HH];  // [W_hh_dec; W_attn[:H]^T]
__device__ __align__(16) bf16 g_Wid_hi[G3H * HH],  g_Wid_lo[G3H * HH];   // W_ih_dec[:, :H]
__device__ __align__(16) bf16 g_Wa2_hi[AA * HH],   g_Wa2_lo[AA * HH];    // W_attn[H:]^T

__device__ __forceinline__ float tanh_fast(float x) {
    float y;
    asm("tanh.approx.f32 %0, %1;" : "=f"(y) : "f"(x));
    return y;
}
__device__ __forceinline__ float sigmoid_f(float x) {
    return 1.f / (1.f + __expf(-x));
}
__device__ __forceinline__ void split_store(float x, bf16* hi, bf16* lo, size_t idx) {
    bf16 h = __float2bfloat16(x);
    hi[idx] = h;
    lo[idx] = __float2bfloat16(x - __bfloat162float(h));
}
__device__ __forceinline__ void mma16816(float* c, const unsigned* a, const unsigned* b) {
    asm volatile(
        "mma.sync.aligned.m16n8k16.row.col.f32.bf16.bf16.f32 "
        "{%0,%1,%2,%3}, {%4,%5,%6,%7}, {%8,%9}, {%0,%1,%2,%3};"
        : "+f"(c[0]), "+f"(c[1]), "+f"(c[2]), "+f"(c[3])
        : "r"(a[0]), "r"(a[1]), "r"(a[2]), "r"(a[3]), "r"(b[0]), "r"(b[1]));
}
__device__ __forceinline__ void cpa16(void* smem, const void* gmem) {
    unsigned s = (unsigned)__cvta_generic_to_shared(smem);
    asm volatile("cp.async.cg.shared.global [%0], [%1], 16;" :: "r"(s), "l"(gmem));
}

// ============== split-bf16 tensor-core GEMM (A pre-split, cp.async double-buffered) ======
// C[M,N] = A @ B^T ; A (M,K) bf16 hi/lo row-major, B (N,K) bf16 hi/lo.
// K == 1024 == A row stride. M%64==0, N%64==0.
#define GBM 64
#define GBN 64
#define GBK 32
#define SSTR 40   // smem row stride in bf16 (80B) -> conflict-free frags, 16B-aligned rows

template<bool HASBIAS>
__global__ __launch_bounds__(128)
void gemm_bf3_kernel(const bf16* __restrict__ Ahi, const bf16* __restrict__ Alo,
                     const bf16* __restrict__ Bhi, const bf16* __restrict__ Blo,
                     const float* __restrict__ bias,
                     float* __restrict__ C, int ldc,
                     int M, int N, int K)
{
    __shared__ __align__(16) bf16 Ah[2][GBM * SSTR];
    __shared__ __align__(16) bf16 Al[2][GBM * SSTR];
    __shared__ __align__(16) bf16 Bh[2][GBN * SSTR];
    __shared__ __align__(16) bf16 Bl[2][GBN * SSTR];

    const int tid  = threadIdx.x;
    const int w    = tid >> 5;
    const int lane = tid & 31;
    const int g    = lane >> 2;
    const int tig  = lane & 3;
    const int m0   = blockIdx.y * GBM;
    const int n0   = blockIdx.x * GBN;

    float acc[4][2][4];
#pragma unroll
    for (int mt = 0; mt < 4; mt++)
#pragma unroll
        for (int nt = 0; nt < 2; nt++)
#pragma unroll
            for (int c = 0; c < 4; c++) acc[mt][nt][c] = 0.f;

    // stage one 64x32 k-tile of all four operands into smem buffer `buf`
    auto stage = [&](int buf, int k0) {
#pragma unroll
        for (int i = 0; i < 2; i++) {
            int f = tid + i * 128;          // 256 uint4 slots per operand
            int r = f >> 2, c = (f & 3) * 8;
            cpa16(&Ah[buf][r * SSTR + c], &Ahi[(size_t)(m0 + r) * K + k0 + c]);
            cpa16(&Al[buf][r * SSTR + c], &Alo[(size_t)(m0 + r) * K + k0 + c]);
            cpa16(&Bh[buf][r * SSTR + c], &Bhi[(size_t)(n0 + r) * K + k0 + c]);
            cpa16(&Bl[buf][r * SSTR + c], &Blo[(size_t)(n0 + r) * K + k0 + c]);
        }
    };

    stage(0, 0);
    asm volatile("cp.async.commit_group;");

    const int nk = K / GBK;
    for (int kt = 0; kt < nk; kt++) {
        const int buf = kt & 1;
        if (kt + 1 < nk) {
            stage(buf ^ 1, (kt + 1) * GBK);
            asm volatile("cp.async.commit_group;");
            asm volatile("cp.async.wait_group 1;");
        } else {
            asm volatile("cp.async.wait_group 0;");
        }
        __syncthreads();

#pragma unroll
        for (int kk = 0; kk < GBK; kk += 16) {
            unsigned ah[4][4], al[4][4], bh[2][2], bl[2][2];
#pragma unroll
            for (int mt = 0; mt < 4; mt++) {
                int r0 = mt * 16 + g;
                ah[mt][0] = *(const unsigned*)&Ah[buf][(r0    ) * SSTR + kk +     tig * 2];
                ah[mt][1] = *(const unsigned*)&Ah[buf][(r0 + 8) * SSTR + kk +     tig * 2];
                ah[mt][2] = *(const unsigned*)&Ah[buf][(r0    ) * SSTR + kk + 8 + tig * 2];
                ah[mt][3] = *(const unsigned*)&Ah[buf][(r0 + 8) * SSTR + kk + 8 + tig * 2];
                al[mt][0] = *(const unsigned*)&Al[buf][(r0    ) * SSTR + kk +     tig * 2];
                al[mt][1] = *(const unsigned*)&Al[buf][(r0 + 8) * SSTR + kk +     tig * 2];
                al[mt][2] = *(const unsigned*)&Al[buf][(r0    ) * SSTR + kk + 8 + tig * 2];
                al[mt][3] = *(const unsigned*)&Al[buf][(r0 + 8) * SSTR + kk + 8 + tig * 2];
            }
#pragma unroll
            for (int nt = 0; nt < 2; nt++) {
                int nb = w * 16 + nt * 8 + g;
                bh[nt][0] = *(const unsigned*)&Bh[buf][nb * SSTR + kk +     tig * 2];
                bh[nt][1] = *(const unsigned*)&Bh[buf][nb * SSTR + kk + 8 + tig * 2];
                bl[nt][0] = *(const unsigned*)&Bl[buf][nb * SSTR + kk +     tig * 2];
                bl[nt][1] = *(const unsigned*)&Bl[buf][nb * SSTR + kk + 8 + tig * 2];
            }
#pragma unroll
            for (int mt = 0; mt < 4; mt++)
#pragma unroll
                for (int nt = 0; nt < 2; nt++) {
                    mma16816(acc[mt][nt], ah[mt], bh[nt]);   // hi*hi
                    mma16816(acc[mt][nt], ah[mt], bl[nt]);   // hi*lo
                    mma16816(acc[mt][nt], al[mt], bh[nt]);   // lo*hi
                }
        }
        __syncthreads();
    }

    // ---- epilogue ----
#pragma unroll
    for (int mt = 0; mt < 4; mt++) {
#pragma unroll
        for (int nt = 0; nt < 2; nt++) {
            int gm = m0 + mt * 16 + g;
            int gn = n0 + w * 16 + nt * 8 + tig * 2;
            float b0 = 0.f, b1 = 0.f;
            if (HASBIAS) { b0 = bias[gn]; b1 = bias[gn + 1]; }
            float2 v0 = make_float2(acc[mt][nt][0] + b0, acc[mt][nt][1] + b1);
            float2 v1 = make_float2(acc[mt][nt][2] + b0, acc[mt][nt][3] + b1);
            *(float2*)&C[(size_t)gm * ldc + gn]       = v0;
            *(float2*)&C[(size_t)(gm + 8) * ldc + gn] = v1;
        }
    }
}

// ---------------- weight conversion kernels (run every replay; keep lean) ----------------
__global__ void conv_nk(const float* __restrict__ W, int ld,
                        bf16* __restrict__ hi, bf16* __restrict__ lo, int Nn, int Kk)
{
    int idx = blockIdx.x * blockDim.x + threadIdx.x;
    if (idx >= Nn * Kk) return;
    int n = idx / Kk, k = idx - n * Kk;
    split_store(W[(size_t)n * ld + k], hi, lo, idx);
}
__global__ void conv_kn(const float* __restrict__ W, int ld,
                        bf16* __restrict__ hi, bf16* __restrict__ lo, int Nn, int Kk)
{
    int idx = blockIdx.x * blockDim.x + threadIdx.x;
    if (idx >= Nn * Kk) return;
    int n = idx / Kk, k = idx - n * Kk;
    split_store(W[(size_t)k * ld + n], hi, lo, idx);
}
// fused: [W_hh_dec ; W_attn[:H]^T] straight to hi/lo
__global__ void conv_wcat(const float* __restrict__ Whh, const float* __restrict__ Wattn,
                          bf16* __restrict__ hi, bf16* __restrict__ lo)
{
    int idx = blockIdx.x * blockDim.x + threadIdx.x;
    if (idx >= NCAT * HH) return;
    int n = idx / HH, k = idx - n * HH;
    float x = (n < G3H) ? Whh[idx] : Wattn[(size_t)k * AA + (n - G3H)];
    split_store(x, hi, lo, idx);
}

// ---------------- fp32 SGEMM for tiny one-time precompute GEMMs ----------------
#define BM 128
#define BN 64
#define BK 16
#define ASTR (BM + 4)
#define BSTR (BN + 4)

__global__ __launch_bounds__(128)
void sgemm_tb_kernel(const float* __restrict__ A, int lda,
                     const float* __restrict__ B, int ldb,
                     float* __restrict__ C, int ldc,
                     int M, int N, int K)
{
    __shared__ float As[BK * ASTR];
    __shared__ float Bs[BK * BSTR];
    const int tid = threadIdx.x;
    const int m0 = blockIdx.y * BM;
    const int n0 = blockIdx.x * BN;
    const int tm = (tid >> 3) * 8;
    const int tn = (tid & 7) * 8;

    float acc[8][8];
#pragma unroll
    for (int i = 0; i < 8; i++)
#pragma unroll
        for (int j = 0; j < 8; j++) acc[i][j] = 0.f;

    for (int k0 = 0; k0 < K; k0 += BK) {
#pragma unroll
        for (int i = 0; i < 4; i++) {
            int f = tid + i * 128;
            int r = f >> 2, kc = (f & 3) * 4;
            int gm = m0 + r;
            float4 v = (gm < M) ? *(const float4*)&A[(size_t)gm * lda + k0 + kc]
                                : make_float4(0.f, 0.f, 0.f, 0.f);
            As[(kc + 0) * ASTR + r] = v.x;
            As[(kc + 1) * ASTR + r] = v.y;
            As[(kc + 2) * ASTR + r] = v.z;
            As[(kc + 3) * ASTR + r] = v.w;
        }
#pragma unroll
        for (int i = 0; i < 2; i++) {
            int f = tid + i * 128;
            int r = f >> 2, kc = (f & 3) * 4;
            float4 v = *(const float4*)&B[(size_t)(n0 + r) * ldb + k0 + kc];
            Bs[(kc + 0) * BSTR + r] = v.x;
            Bs[(kc + 1) * BSTR + r] = v.y;
            Bs[(kc + 2) * BSTR + r] = v.z;
            Bs[(kc + 3) * BSTR + r] = v.w;
        }
        __syncthreads();
#pragma unroll
        for (int kk = 0; kk < BK; kk++) {
            float av[8], bv[8];
#pragma unroll
            for (int i = 0; i < 4; i++) ((float2*)av)[i] = *(float2*)&As[kk * ASTR + tm + i * 2];
#pragma unroll
            for (int j = 0; j < 4; j++) ((float2*)bv)[j] = *(float2*)&Bs[kk * BSTR + tn + j * 2];
#pragma unroll
            for (int i = 0; i < 8; i++)
#pragma unroll
                for (int j = 0; j < 8; j++)
                    acc[i][j] = fmaf(av[i], bv[j], acc[i][j]);
        }
        __syncthreads();
    }
#pragma unroll
    for (int i = 0; i < 8; i++) {
        int gm = m0 + tm + i;
        if (gm >= M) continue;
        float* crow = &C[(size_t)gm * ldc + n0 + tn];
#pragma unroll
        for (int j = 0; j < 8; j++) crow[j] = acc[i][j];
    }
}

// ---------------- init ----------------
__global__ void init_kernel(const int* __restrict__ target, float* __restrict__ out)
{
    int i = blockIdx.x * blockDim.x + threadIdx.x;
    if (i < BB * HH) {
        g_h[i] = 0.f;
        g_h_hi[i] = __float2bfloat16(0.f);
        g_h_lo[i] = __float2bfloat16(0.f);
    }
    if (i < BB * VTGT) out[i] = ((i % VTGT) == STARTTOK) ? 1.f : 0.f;
    if (i < BB) g_x[i] = target[i];
}

// ---------------- encoder GRU cell (also emits split-bf16 h and enc_ops) ----------------
__global__ void gru_enc_cell(const int* __restrict__ source, int s,
                             const float* __restrict__ b_ih,
                             const float* __restrict__ b_hh)
{
    int idx = blockIdx.x * blockDim.x + threadIdx.x;
    if (idx >= BB * HH) return;
    int b = idx / HH, j = idx - b * HH;
    int tok = source[s * BB + b];
    const float* P  = &g_P_enc[(size_t)tok * G3H];
    const float* gh = &g_gh[(size_t)b * G3H];
    float gir = P[j]          + b_ih[j];
    float giz = P[HH + j]     + b_ih[HH + j];
    float gin = P[2 * HH + j] + b_ih[2 * HH + j];
    float ghr = gh[j]          + b_hh[j];
    float ghz = gh[HH + j]     + b_hh[HH + j];
    float ghn = gh[2 * HH + j] + b_hh[2 * HH + j];
    float r = sigmoid_f(gir + ghr);
    float z = sigmoid_f(giz + ghz);
    float n = tanhf(gin + r * ghn);
    float hv = (1.f - z) * n + z * g_h[idx];
    g_h[idx] = hv;
    split_store(hv, g_h_hi, g_h_lo, idx);
    size_t eidx = (size_t)s * BB * HH + idx;
    g_enc_ops[eidx] = hv;
    split_store(hv, g_enc_hi, g_enc_lo, eidx);
}

// ---------------- decoder GRU cell ----------------
__global__ void gru_dec_cell(const float* __restrict__ b_ih,
                             const float* __restrict__ b_hh)
{
    int idx = blockIdx.x * blockDim.x + threadIdx.x;
    if (idx >= BB * HH) return;
    int b = idx / HH, j = idx - b * HH;
    int tok = g_x[b];
    const float* P  = &g_P_dec[(size_t)tok * G3H];
    const float* gi = &g_gi[(size_t)b * G3H];
    const float* gh = &g_ghp[(size_t)b * NCAT];
    float gir = gi[j]          + P[j]          + b_ih[j];
    float giz = gi[HH + j]     + P[HH + j]     + b_ih[HH + j];
    float gin = gi[2 * HH + j] + P[2 * HH + j] + b_ih[2 * HH + j];
    float ghr = gh[j]          + b_hh[j];
    float ghz = gh[HH + j]     + b_hh[HH + j];
    float ghn = gh[2 * HH + j] + b_hh[2 * HH + j];
    float r = sigmoid_f(gir + ghr);
    float z = sigmoid_f(giz + ghz);
    float n = tanhf(gin + r * ghn);
    float hv = (1.f - z) * n + z * g_h[idx];
    g_h[idx] = hv;
    split_store(hv, g_h_hi, g_h_lo, idx);
}

// ---------------- fused attention: scores -> softmax -> context (+ split ctx) ----------
__global__ __launch_bounds__(1024)
void attn_fused_kernel(const float* __restrict__ v_attn,
                       float* __restrict__ attn_plane /* (B,S) */)
{
    int b = blockIdx.x;
    int tid = threadIdx.x;
    int w = tid >> 5, lane = tid & 31;

    __shared__ float hp_s[AA];
    __shared__ float v_s[AA];
    __shared__ float sc[SS];
    __shared__ float alpha_s[SS];

    hp_s[tid] = g_ghp[(size_t)b * NCAT + G3H + tid];
    v_s[tid]  = v_attn[tid];
    __syncthreads();

    const float* ep = &g_enc_proj[((size_t)w * BB + b) * AA];
    float sum = 0.f;
#pragma unroll
    for (int i = 0; i < AA / 32; i++) {
        int a = i * 32 + lane;
        sum += tanh_fast(ep[a] + hp_s[a]) * v_s[a];
    }
#pragma unroll
    for (int off = 16; off > 0; off >>= 1)
        sum += __shfl_xor_sync(0xffffffffu, sum, off);
    if (lane == 0) sc[w] = sum;
    __syncthreads();

    if (w == 0) {
        float v = sc[lane];
        float mx = v;
#pragma unroll
        for (int off = 16; off > 0; off >>= 1)
            mx = fmaxf(mx, __shfl_xor_sync(0xffffffffu, mx, off));
        float e = __expf(v - mx);
        float ssum = e;
#pragma unroll
        for (int off = 16; off > 0; off >>= 1)
            ssum += __shfl_xor_sync(0xffffffffu, ssum, off);
        float al = e / ssum;
        alpha_s[lane] = al;
        attn_plane[b * SS + lane] = al;
    }
    __syncthreads();

    float accv = 0.f;
#pragma unroll
    for (int s = 0; s < SS; s++)
        accv = fmaf(alpha_s[s], g_enc_ops[((size_t)s * BB + b) * HH + tid], accv);
    size_t cidx = (size_t)b * HH + tid;
    g_ctx[cidx] = accv;
    split_store(accv, g_ctx_hi, g_ctx_lo, cidx);
}

// ---------------- logits + next-token ----------------
__global__ void logits_kernel(const float* __restrict__ W_out,
                              const float* __restrict__ b_out,
                              const int* __restrict__ target,
                              const int* __restrict__ tf_ptr,
                              int t, float* __restrict__ out)
{
    int b = blockIdx.x;
    __shared__ float hs[HH];
    for (int k = threadIdx.x; k < HH; k += 128) hs[k] = g_h[(size_t)b * HH + k];
    __syncthreads();
    int v = threadIdx.x;
    float lg = -1e30f;
    if (v < VTGT) {
        float acc = b_out[v];
#pragma unroll 8
        for (int k = 0; k < HH; k++) acc = fmaf(hs[k], W_out[k * VTGT + v], acc);
        out[(size_t)t * BB * VTGT + (size_t)b * VTGT + v] = acc;
        lg = acc;
    }
    __shared__ float sv[128];
    __shared__ int   si[128];
    sv[threadIdx.x] = lg;
    si[threadIdx.x] = v;
    __syncthreads();
#pragma unroll
    for (int off = 64; off > 0; off >>= 1) {
        if (threadIdx.x < off) {
            float vo = sv[threadIdx.x + off];
            int   io = si[threadIdx.x + off];
            if (vo > sv[threadIdx.x] || (vo == sv[threadIdx.x] && io < si[threadIdx.x])) {
                sv[threadIdx.x] = vo;
                si[threadIdx.x] = io;
            }
        }
        __syncthreads();
    }
    if (threadIdx.x == 0)
        g_x[b] = (*tf_ptr != 0) ? target[t * BB + b] : si[0];
}

// ---------------- host-side orchestration ----------------
static inline void gemm_tc(const bf16* Ahi, const bf16* Alo,
                           const bf16* Bhi, const bf16* Blo,
                           const float* bias, float* C, int ldc, int M, int N, int K)
{
    dim3 grid(N / GBN, M / GBM);
    if (bias)
        gemm_bf3_kernel<true><<<grid, 128>>>(Ahi, Alo, Bhi, Blo, bias, C, ldc, M, N, K);
    else
        gemm_bf3_kernel<false><<<grid, 128>>>(Ahi, Alo, Bhi, Blo, nullptr, C, ldc, M, N, K);
}

extern "C" void kernel_launch(void* const* d_in, const int* in_sizes, int n_in,
                              void* d_out, int out_size)
{
    const int*   source   = (const int*)  d_in[0];
    const int*   target   = (const int*)  d_in[1];
    const int*   tf       = (const int*)  d_in[2];
    const float* emb_src  = (const float*)d_in[3];
    const float* W_ih_enc = (const float*)d_in[4];
    const float* W_hh_enc = (const float*)d_in[5];
    const float* b_ih_enc = (const float*)d_in[6];
    const float* b_hh_enc = (const float*)d_in[7];
    const float* emb_tgt  = (const float*)d_in[8];
    const float* W_attn   = (const float*)d_in[9];
    const float* b_attn   = (const float*)d_in[10];
    const float* v_attn   = (const float*)d_in[11];
    const float* W_ih_dec = (const float*)d_in[12];
    const float* W_hh_dec = (const float*)d_in[13];
    const float* b_ih_dec = (const float*)d_in[14];
    const float* b_hh_dec = (const float*)d_in[15];
    const float* W_out    = (const float*)d_in[16];
    const float* b_out    = (const float*)d_in[17];

    float* out      = (float*)d_out;
    float* attn_out = out + (size_t)TT * BB * VTGT;

    float *pP_enc, *pP_dec, *pproj, *pgh, *pghp, *pgi;
    cudaGetSymbolAddress((void**)&pP_enc, g_P_enc);
    cudaGetSymbolAddress((void**)&pP_dec, g_P_dec);
    cudaGetSymbolAddress((void**)&pproj,  g_enc_proj);
    cudaGetSymbolAddress((void**)&pgh,    g_gh);
    cudaGetSymbolAddress((void**)&pghp,   g_ghp);
    cudaGetSymbolAddress((void**)&pgi,    g_gi);

    bf16 *ph_h, *ph_l, *pe_h, *pe_l, *pc_h, *pc_l;
    cudaGetSymbolAddress((void**)&ph_h, g_h_hi);
    cudaGetSymbolAddress((void**)&ph_l, g_h_lo);
    cudaGetSymbolAddress((void**)&pe_h, g_enc_hi);
    cudaGetSymbolAddress((void**)&pe_l, g_enc_lo);
    cudaGetSymbolAddress((void**)&pc_h, g_ctx_hi);
    cudaGetSymbolAddress((void**)&pc_l, g_ctx_lo);

    bf16 *pWhe_h, *pWhe_l, *pWct_h, *pWct_l, *pWid_h, *pWid_l, *pWa2_h, *pWa2_l;
    cudaGetSymbolAddress((void**)&pWhe_h, g_Whe_hi);
    cudaGetSymbolAddress((void**)&pWhe_l, g_Whe_lo);
    cudaGetSymbolAddress((void**)&pWct_h, g_Wct_hi);
    cudaGetSymbolAddress((void**)&pWct_l, g_Wct_lo);
    cudaGetSymbolAddress((void**)&pWid_h, g_Wid_hi);
    cudaGetSymbolAddress((void**)&pWid_l, g_Wid_lo);
    cudaGetSymbolAddress((void**)&pWa2_h, g_Wa2_hi);
    cudaGetSymbolAddress((void**)&pWa2_l, g_Wa2_lo);

    // init: h=0 (+splits), outputs row 0, x = target[0]
    init_kernel<<<(BB * HH + 255) / 256, 256>>>(target, out);

    // token-projection tables (fold embedding gather through the input GEMMs)
    {
        dim3 g1(G3H / BN, (VSRC + BM - 1) / BM);
        sgemm_tb_kernel<<<g1, 128>>>(emb_src, EE, W_ih_enc, EE, pP_enc, G3H, VSRC, G3H, EE);
        dim3 g2(G3H / BN, (VTGT + BM - 1) / BM);
        sgemm_tb_kernel<<<g2, 128>>>(emb_tgt, EE, W_ih_dec + HH, HH + EE, pP_dec, G3H, VTGT, G3H, EE);
    }

    // split-bf16 weight conversions
    conv_nk  <<<(G3H  * HH + 255) / 256, 256>>>(W_hh_enc, HH,      pWhe_h, pWhe_l, G3H,  HH);
    conv_wcat<<<(NCAT * HH + 255) / 256, 256>>>(W_hh_dec, W_attn,  pWct_h, pWct_l);
    conv_nk  <<<(G3H  * HH + 255) / 256, 256>>>(W_ih_dec, HH + EE, pWid_h, pWid_l, G3H,  HH);
    conv_kn  <<<(AA   * HH + 255) / 256, 256>>>(W_attn + (size_t)HH * AA, AA, pWa2_h, pWa2_l, AA, HH);

    // ---------------- encoder ----------------
    for (int s = 0; s < SS; s++) {
        gemm_tc(ph_h, ph_l, pWhe_h, pWhe_l, nullptr, pgh, G3H, BB, G3H, HH);
        gru_enc_cell<<<(BB * HH + 255) / 256, 256>>>(source, s, b_ih_enc, b_hh_enc);
    }

    // step-invariant half of attention energy (+ bias folded in)
    gemm_tc(pe_h, pe_l, pWa2_h, pWa2_l, b_attn, pproj, AA, SS * BB, AA, HH);

    // ---------------- decoder ----------------
    for (int t = 1; t < TT; t++) {
        gemm_tc(ph_h, ph_l, pWct_h, pWct_l, nullptr, pghp, NCAT, BB, NCAT, HH);
        attn_fused_kernel<<<BB, 1024>>>(v_attn, attn_out + (size_t)(t - 1) * BB * SS);
        gemm_tc(pc_h, pc_l, pWid_h, pWid_l, nullptr, pgi, G3H, BB, G3H, HH);
        gru_dec_cell<<<(BB * HH + 255) / 256, 256>>>(b_ih_dec, b_hh_dec);
        logits_kernel<<<BB, 128>>>(W_out, b_out, target, tf, t, out);
    }
}